// round 1
// baseline (speedup 1.0000x reference)
#include <cuda_runtime.h>

// GRUController: B=8192, T_in=512, N_IN=2, H=64, T_out=180, 2-layer enc + 2-layer dec.
// Persistent per-CTA fp32 GRU. grid=128 CTAs x 64 rows, 256 threads, ~185KB dyn smem.
// Each thread: 4 rows x 4 hidden cols, 64 register accumulators (r,z,n_ih,n_hh).

#define TIN   512
#define TOUT  180
#define H     64
#define ROWS  64
#define NT    256

// smem layout (floats)
#define OFF_WT0   0        // 64*192   layer0 Whh^T  [k][j]
#define OFF_WC1   12288    // 128*192  layer1 [Wih;Whh]^T
#define OFF_HT0   36864    // 64*64    h0 transposed [k][r]
#define OFF_HT1   40960    // 64*64
#define OFF_B0    45056    // 256: bR,bZ,bIN,bHN (layer0)
#define OFF_B1    45312    // 256
#define OFF_W0S   45568    // 384: layer0 ih weights (row-major [j][c])
#define OFF_XST   45952    // 128: staged x, [c][r]
#define OFF_PREV  46080    // 64
#define OFF_OUTW  46144    // 64
#define SMEM_FLOATS 46208
#define SMEM_BYTES  (SMEM_FLOATS * 4)

__device__ __forceinline__ float sigm_f(float x) {
    return 1.0f / (1.0f + __expf(-x));
}
__device__ __forceinline__ float tanh_f(float x) {
    return 2.0f / (1.0f + __expf(-2.0f * x)) - 1.0f;
}

__device__ __forceinline__ void fma16(float (&A)[4][4], const float4 hv, const float4 wv) {
    const float h[4] = {hv.x, hv.y, hv.z, hv.w};
    const float w[4] = {wv.x, wv.y, wv.z, wv.w};
#pragma unroll
    for (int ci = 0; ci < 4; ci++)
#pragma unroll
        for (int ri = 0; ri < 4; ri++)
            A[ci][ri] += h[ri] * w[ci];
}

// accumulate A_r,A_z,A_n over 64-wide hidden contraction
__device__ __forceinline__ void kloop64(const float* __restrict__ src,   // [k][r] 64x64
                                        const float* __restrict__ W,     // [k][192]
                                        float (&aR)[4][4], float (&aZ)[4][4],
                                        float (&aN)[4][4], int r0, int j0) {
#pragma unroll 4
    for (int k = 0; k < 64; k++) {
        float4 hv = *(const float4*)&src[k * 64 + r0];
        float4 wr = *(const float4*)&W[k * 192 + j0];
        float4 wz = *(const float4*)&W[k * 192 + 64 + j0];
        float4 wn = *(const float4*)&W[k * 192 + 128 + j0];
        fma16(aR, hv, wr);
        fma16(aZ, hv, wz);
        fma16(aN, hv, wn);
    }
}

__device__ __forceinline__ void init_bias(float (&aR)[4][4], float (&aZ)[4][4],
                                          float (&nI)[4][4], float (&nH)[4][4],
                                          const float* __restrict__ b, int j0) {
#pragma unroll
    for (int ci = 0; ci < 4; ci++) {
        int j = j0 + ci;
        float br = b[j], bz = b[64 + j], bi = b[128 + j], bh = b[192 + j];
#pragma unroll
        for (int ri = 0; ri < 4; ri++) {
            aR[ci][ri] = br; aZ[ci][ri] = bz; nI[ci][ri] = bi; nH[ci][ri] = bh;
        }
    }
}

// gates + in-place state update for one layer. ht: [j][r] view == [k][r].
__device__ __forceinline__ void gru_update(float* ht, float (&aR)[4][4], float (&aZ)[4][4],
                                           float (&nI)[4][4], float (&nH)[4][4],
                                           int r0, int j0) {
    float4 hold[4];
#pragma unroll
    for (int ci = 0; ci < 4; ci++)
        hold[ci] = *(float4*)&ht[(j0 + ci) * 64 + r0];
    __syncthreads();   // all reads of old state done chip... CTA-wide
#pragma unroll
    for (int ci = 0; ci < 4; ci++) {
        const float hp[4] = {hold[ci].x, hold[ci].y, hold[ci].z, hold[ci].w};
        float o[4];
#pragma unroll
        for (int ri = 0; ri < 4; ri++) {
            float r = sigm_f(aR[ci][ri]);
            float z = sigm_f(aZ[ci][ri]);
            float n = tanh_f(nI[ci][ri] + r * nH[ci][ri]);
            o[ri] = (1.0f - z) * n + z * hp[ri];
        }
        *(float4*)&ht[(j0 + ci) * 64 + r0] = make_float4(o[0], o[1], o[2], o[3]);
    }
    __syncthreads();
}

__device__ void load_weights(float* __restrict__ sm,
                             const float* __restrict__ Wih0, int nin,
                             const float* __restrict__ Whh0,
                             const float* __restrict__ bih0, const float* __restrict__ bhh0,
                             const float* __restrict__ Wih1, const float* __restrict__ Whh1,
                             const float* __restrict__ bih1, const float* __restrict__ bhh1,
                             int tid) {
    float* wt0 = sm + OFF_WT0;
    float* wc1 = sm + OFF_WC1;
    float* b0  = sm + OFF_B0;
    float* b1  = sm + OFF_B1;
    float* w0s = sm + OFF_W0S;
    for (int i = tid; i < 12288; i += NT) { int j = i >> 6, k = i & 63; wt0[k * 192 + j] = Whh0[i]; }
    for (int i = tid; i < 12288; i += NT) { int j = i >> 6, k = i & 63; wc1[k * 192 + j] = Wih1[i]; }
    for (int i = tid; i < 12288; i += NT) { int j = i >> 6, k = i & 63; wc1[(64 + k) * 192 + j] = Whh1[i]; }
    for (int i = tid; i < 192 * nin; i += NT) w0s[i] = Wih0[i];
    if (tid < 64) {
        b0[tid]       = bih0[tid]       + bhh0[tid];
        b0[64 + tid]  = bih0[64 + tid]  + bhh0[64 + tid];
        b0[128 + tid] = bih0[128 + tid];
        b0[192 + tid] = bhh0[128 + tid];
        b1[tid]       = bih1[tid]       + bhh1[tid];
        b1[64 + tid]  = bih1[64 + tid]  + bhh1[64 + tid];
        b1[128 + tid] = bih1[128 + tid];
        b1[192 + tid] = bhh1[128 + tid];
    }
}

extern "C" __global__ void __launch_bounds__(NT, 1)
gru_controller_kernel(const float* __restrict__ x,
                      const float* eWih0, const float* eWhh0, const float* ebih0, const float* ebhh0,
                      const float* eWih1, const float* eWhh1, const float* ebih1, const float* ebhh1,
                      const float* dWih0, const float* dWhh0, const float* dbih0, const float* dbhh0,
                      const float* dWih1, const float* dWhh1, const float* dbih1, const float* dbhh1,
                      const float* __restrict__ outW, const float* __restrict__ outb,
                      float* __restrict__ out) {
    extern __shared__ float sm[];
    float* wt0  = sm + OFF_WT0;
    float* wc1  = sm + OFF_WC1;
    float* ht0  = sm + OFF_HT0;
    float* ht1  = sm + OFF_HT1;
    float* b0   = sm + OFF_B0;
    float* b1   = sm + OFF_B1;
    float* w0s  = sm + OFF_W0S;
    float* xst  = sm + OFF_XST;
    float* prevb = sm + OFF_PREV;
    float* outw = sm + OFF_OUTW;

    const int tid = threadIdx.x;
    const int rt = tid & 15, ct = tid >> 4;
    const int r0 = rt * 4, j0 = ct * 4;
    const int rbase = blockIdx.x * ROWS;

    // zero h0,h1 (contiguous 8192 floats)
    for (int i = tid; i < 8192; i += NT) ht0[i] = 0.0f;
    load_weights(sm, eWih0, 2, eWhh0, ebih0, ebhh0, eWih1, eWhh1, ebih1, ebhh1, tid);
    if (tid < 64) outw[tid] = outW[tid];
    __syncthreads();

    float aR[4][4], aZ[4][4], nI[4][4], nH[4][4];

    // ===================== encoder =====================
    for (int t = 0; t < TIN; t++) {
        if (tid < 128) {
            int r = tid >> 1, c = tid & 1;
            xst[c * 64 + r] = x[((long)(rbase + r) * TIN + t) * 2 + c];
        }
        __syncthreads();

        // layer 0: init = bias + x @ Wih0^T
        {
            float4 x0v = *(float4*)&xst[r0];
            float4 x1v = *(float4*)&xst[64 + r0];
            const float xa[4] = {x0v.x, x0v.y, x0v.z, x0v.w};
            const float xb[4] = {x1v.x, x1v.y, x1v.z, x1v.w};
            init_bias(aR, aZ, nI, nH, b0, j0);
#pragma unroll
            for (int ci = 0; ci < 4; ci++) {
                int j = j0 + ci;
                float wr0 = w0s[2 * j],           wr1 = w0s[2 * j + 1];
                float wz0 = w0s[2 * (64 + j)],    wz1 = w0s[2 * (64 + j) + 1];
                float wn0 = w0s[2 * (128 + j)],   wn1 = w0s[2 * (128 + j) + 1];
#pragma unroll
                for (int ri = 0; ri < 4; ri++) {
                    aR[ci][ri] += xa[ri] * wr0 + xb[ri] * wr1;
                    aZ[ci][ri] += xa[ri] * wz0 + xb[ri] * wz1;
                    nI[ci][ri] += xa[ri] * wn0 + xb[ri] * wn1;
                }
            }
        }
        kloop64(ht0, wt0, aR, aZ, nH, r0, j0);          // hidden part -> r,z,n_hh
        gru_update(ht0, aR, aZ, nI, nH, r0, j0);

        // layer 1: K=128 concat [h0_new ; h1]
        init_bias(aR, aZ, nI, nH, b1, j0);
        kloop64(ht0, wc1, aR, aZ, nI, r0, j0);          // ih part (n -> nI)
        kloop64(ht1, wc1 + 64 * 192, aR, aZ, nH, r0, j0); // hh part (n -> nH)
        gru_update(ht1, aR, aZ, nI, nH, r0, j0);
    }

    // ===================== swap to decoder weights =====================
    load_weights(sm, dWih0, 1, dWhh0, dbih0, dbhh0, dWih1, dWhh1, dbih1, dbhh1, tid);
    if (tid < 64) prevb[tid] = 0.0f;
    __syncthreads();
    const float ob = outb[0];

    // ===================== decoder =====================
    for (int t = 0; t < TOUT; t++) {
        // layer 0: init = bias + prev * Wih0 (nin=1)
        {
            float4 pv = *(float4*)&prevb[r0];
            const float p[4] = {pv.x, pv.y, pv.z, pv.w};
            init_bias(aR, aZ, nI, nH, b0, j0);
#pragma unroll
            for (int ci = 0; ci < 4; ci++) {
                int j = j0 + ci;
                float wr = w0s[j], wz = w0s[64 + j], wn = w0s[128 + j];
#pragma unroll
                for (int ri = 0; ri < 4; ri++) {
                    aR[ci][ri] += p[ri] * wr;
                    aZ[ci][ri] += p[ri] * wz;
                    nI[ci][ri] += p[ri] * wn;
                }
            }
        }
        kloop64(ht0, wt0, aR, aZ, nH, r0, j0);
        gru_update(ht0, aR, aZ, nI, nH, r0, j0);

        init_bias(aR, aZ, nI, nH, b1, j0);
        kloop64(ht0, wc1, aR, aZ, nI, r0, j0);
        kloop64(ht1, wc1 + 64 * 192, aR, aZ, nH, r0, j0);
        gru_update(ht1, aR, aZ, nI, nH, r0, j0);

        // output head: cv = h1 @ outW^T + outb ; feed back as prev
        if (tid < 64) {
            float acc = ob;
#pragma unroll 8
            for (int j = 0; j < 64; j++) acc += ht1[j * 64 + tid] * outw[j];
            prevb[tid] = acc;
            out[(long)(rbase + tid) * TOUT + t] = acc;
        }
        __syncthreads();
    }
}

extern "C" void kernel_launch(void* const* d_in, const int* in_sizes, int n_in,
                              void* d_out, int out_size) {
    const float* x     = (const float*)d_in[0];
    const float* eWih0 = (const float*)d_in[1];
    const float* eWhh0 = (const float*)d_in[2];
    const float* ebih0 = (const float*)d_in[3];
    const float* ebhh0 = (const float*)d_in[4];
    const float* eWih1 = (const float*)d_in[5];
    const float* eWhh1 = (const float*)d_in[6];
    const float* ebih1 = (const float*)d_in[7];
    const float* ebhh1 = (const float*)d_in[8];
    const float* dWih0 = (const float*)d_in[9];
    const float* dWhh0 = (const float*)d_in[10];
    const float* dbih0 = (const float*)d_in[11];
    const float* dbhh0 = (const float*)d_in[12];
    const float* dWih1 = (const float*)d_in[13];
    const float* dWhh1 = (const float*)d_in[14];
    const float* dbih1 = (const float*)d_in[15];
    const float* dbhh1 = (const float*)d_in[16];
    const float* outW  = (const float*)d_in[17];
    const float* outb  = (const float*)d_in[18];
    float* out = (float*)d_out;

    cudaFuncSetAttribute(gru_controller_kernel,
                         cudaFuncAttributeMaxDynamicSharedMemorySize, SMEM_BYTES);
    gru_controller_kernel<<<128, NT, SMEM_BYTES>>>(
        x, eWih0, eWhh0, ebih0, ebhh0, eWih1, eWhh1, ebih1, ebhh1,
        dWih0, dWhh0, dbih0, dbhh0, dWih1, dWhh1, dbih1, dbhh1,
        outW, outb, out);
}

// round 4
// speedup vs baseline: 2.1319x; 2.1319x over previous
#include <cuda_runtime.h>

// GRUController: B=8192, T_in=512, N_IN=2, H=64, T_out=180.
// Persistent per-CTA fp32 GRU, FFMA2 (fma.rn.f32x2) inner loops.
// grid=128 CTAs x 64 rows, 256 threads, ~218KB dyn smem, double-buffered state.

typedef unsigned long long u64;

#define TIN   512
#define TOUT  180
#define NT    256

// smem layout (float indices)
#define OFF_WT0   0        // 64*192   layer0 Whh^T [k][j]
#define OFF_WC1   12288    // 128*192  layer1 [Wih;Whh]^T
#define OFF_H0A   36864    // 64*64 h0 ping
#define OFF_H0B   40960    // 64*64 h0 pong
#define OFF_H1A   45056
#define OFF_H1B   49152
#define OFF_B0    53248    // 256: bR,bZ,bIN,bHN (layer0)
#define OFF_B1    53504    // 256
#define OFF_W0S   53760    // 384: layer0 ih weights transposed [c][g*64+j]
#define OFF_XST   54144    // 2 x 128 staged x, [c][r]
#define OFF_PREV  54400    // 64
#define OFF_OUTW  54464    // 64
#define SMEM_FLOATS 54528
#define SMEM_BYTES  (SMEM_FLOATS * 4)

__device__ __forceinline__ u64 pack2(float lo, float hi) {
    u64 r; asm("mov.b64 %0,{%1,%2};" : "=l"(r) : "f"(lo), "f"(hi)); return r;
}
__device__ __forceinline__ void unpack2(u64 v, float& lo, float& hi) {
    asm("mov.b64 {%0,%1},%2;" : "=f"(lo), "=f"(hi) : "l"(v));
}
__device__ __forceinline__ u64 fma2(u64 a, u64 b, u64 c) {
    u64 d; asm("fma.rn.f32x2 %0,%1,%2,%3;" : "=l"(d) : "l"(a), "l"(b), "l"(c)); return d;
}
__device__ __forceinline__ float tanh_t(float x) {
    float y; asm("tanh.approx.f32 %0,%1;" : "=f"(y) : "f"(x)); return y;
}
__device__ __forceinline__ float sigm_t(float x) {
    return fmaf(tanh_t(0.5f * x), 0.5f, 0.5f);
}

// packed K=64 contraction: acc[p][ri] over column-pairs p, rows ri
__device__ __forceinline__ void kloop64p(const float* __restrict__ src,   // [k][r] 64x64
                                         const float* __restrict__ W,     // [k][192]
                                         u64 (&aR)[2][4], u64 (&aZ)[2][4], u64 (&aN)[2][4],
                                         int r0, int j0) {
#pragma unroll 2
    for (int k = 0; k < 64; k++) {
        float4 hv = *(const float4*)&src[k * 64 + r0];
        ulonglong2 wr = *(const ulonglong2*)&W[k * 192 + j0];
        ulonglong2 wz = *(const ulonglong2*)&W[k * 192 + 64 + j0];
        ulonglong2 wn = *(const ulonglong2*)&W[k * 192 + 128 + j0];
        u64 hd[4] = {pack2(hv.x, hv.x), pack2(hv.y, hv.y), pack2(hv.z, hv.z), pack2(hv.w, hv.w)};
        u64 wrp[2] = {wr.x, wr.y}, wzp[2] = {wz.x, wz.y}, wnp[2] = {wn.x, wn.y};
#pragma unroll
        for (int p = 0; p < 2; p++)
#pragma unroll
            for (int ri = 0; ri < 4; ri++) {
                aR[p][ri] = fma2(hd[ri], wrp[p], aR[p][ri]);
                aZ[p][ri] = fma2(hd[ri], wzp[p], aZ[p][ri]);
                aN[p][ri] = fma2(hd[ri], wnp[p], aN[p][ri]);
            }
    }
}

__device__ __forceinline__ void init_b(const float* __restrict__ b,
                                       u64 (&aR)[2][4], u64 (&aZ)[2][4],
                                       u64 (&nI)[2][4], u64 (&nH)[2][4], int j0) {
#pragma unroll
    for (int p = 0; p < 2; p++) {
        int base = j0 + 2 * p;
        u64 bR = *(const u64*)&b[base];
        u64 bZ = *(const u64*)&b[64 + base];
        u64 bI = *(const u64*)&b[128 + base];
        u64 bH = *(const u64*)&b[192 + base];
#pragma unroll
        for (int ri = 0; ri < 4; ri++) { aR[p][ri] = bR; aZ[p][ri] = bZ; nI[p][ri] = bI; nH[p][ri] = bH; }
    }
}

// gates + state update; reads old h from hsrc, writes new h to hdst (no sync inside)
__device__ __forceinline__ void gru_update2(const float* __restrict__ hsrc, float* __restrict__ hdst,
                                            u64 (&aR)[2][4], u64 (&aZ)[2][4],
                                            u64 (&nI)[2][4], u64 (&nH)[2][4], int r0, int j0) {
#pragma unroll
    for (int p = 0; p < 2; p++) {
        int c0 = j0 + 2 * p, c1 = c0 + 1;
        float4 hA = *(const float4*)&hsrc[c0 * 64 + r0];
        float4 hB = *(const float4*)&hsrc[c1 * 64 + r0];
        const float hAa[4] = {hA.x, hA.y, hA.z, hA.w};
        const float hBa[4] = {hB.x, hB.y, hB.z, hB.w};
        float oA[4], oB[4];
#pragma unroll
        for (int ri = 0; ri < 4; ri++) {
            float arl, arh, azl, azh, nil, nih, nhl, nhh;
            unpack2(aR[p][ri], arl, arh);
            unpack2(aZ[p][ri], azl, azh);
            unpack2(nI[p][ri], nil, nih);
            unpack2(nH[p][ri], nhl, nhh);
            float r0v = sigm_t(arl), r1v = sigm_t(arh);
            float z0  = sigm_t(azl), z1  = sigm_t(azh);
            float n0  = tanh_t(fmaf(r0v, nhl, nil));
            float n1  = tanh_t(fmaf(r1v, nhh, nih));
            oA[ri] = fmaf(z0, hAa[ri] - n0, n0);
            oB[ri] = fmaf(z1, hBa[ri] - n1, n1);
        }
        *(float4*)&hdst[c0 * 64 + r0] = make_float4(oA[0], oA[1], oA[2], oA[3]);
        *(float4*)&hdst[c1 * 64 + r0] = make_float4(oB[0], oB[1], oB[2], oB[3]);
    }
}

__device__ void load_weights(float* __restrict__ sm,
                             const float* __restrict__ Wih0, int nin,
                             const float* __restrict__ Whh0,
                             const float* __restrict__ bih0, const float* __restrict__ bhh0,
                             const float* __restrict__ Wih1, const float* __restrict__ Whh1,
                             const float* __restrict__ bih1, const float* __restrict__ bhh1,
                             int tid) {
    float* wt0 = sm + OFF_WT0;
    float* wc1 = sm + OFF_WC1;
    float* b0  = sm + OFF_B0;
    float* b1  = sm + OFF_B1;
    float* w0s = sm + OFF_W0S;
    for (int i = tid; i < 12288; i += NT) { int j = i >> 6, k = i & 63; wt0[k * 192 + j] = Whh0[i]; }
    for (int i = tid; i < 12288; i += NT) { int j = i >> 6, k = i & 63; wc1[k * 192 + j] = Wih1[i]; }
    for (int i = tid; i < 12288; i += NT) { int j = i >> 6, k = i & 63; wc1[(64 + k) * 192 + j] = Whh1[i]; }
    // layer0 ih weights transposed: w0s[c*192 + g*64 + j] = Wih0[(g*64+j)*nin + c]
    for (int i = tid; i < 192 * nin; i += NT) { int c = i / 192, gj = i % 192; w0s[i] = Wih0[gj * nin + c]; }
    if (tid < 64) {
        b0[tid]       = bih0[tid]       + bhh0[tid];
        b0[64 + tid]  = bih0[64 + tid]  + bhh0[64 + tid];
        b0[128 + tid] = bih0[128 + tid];
        b0[192 + tid] = bhh0[128 + tid];
        b1[tid]       = bih1[tid]       + bhh1[tid];
        b1[64 + tid]  = bih1[64 + tid]  + bhh1[64 + tid];
        b1[128 + tid] = bih1[128 + tid];
        b1[192 + tid] = bhh1[128 + tid];
    }
}

extern "C" __global__ void __launch_bounds__(NT, 1)
gru_controller_kernel(const float* __restrict__ x,
                      const float* eWih0, const float* eWhh0, const float* ebih0, const float* ebhh0,
                      const float* eWih1, const float* eWhh1, const float* ebih1, const float* ebhh1,
                      const float* dWih0, const float* dWhh0, const float* dbih0, const float* dbhh0,
                      const float* dWih1, const float* dWhh1, const float* dbih1, const float* dbhh1,
                      const float* __restrict__ outW, const float* __restrict__ outb,
                      float* __restrict__ out) {
    extern __shared__ float sm[];
    float* wt0   = sm + OFF_WT0;
    float* wc1   = sm + OFF_WC1;
    float* b0    = sm + OFF_B0;
    float* b1    = sm + OFF_B1;
    float* w0s   = sm + OFF_W0S;
    float* xst   = sm + OFF_XST;
    float* prevb = sm + OFF_PREV;
    float* outw  = sm + OFF_OUTW;

    const int tid = threadIdx.x;
    const int rt = tid & 15, ct = tid >> 4;
    const int r0 = rt * 4, j0 = ct * 4;
    const int rbase = blockIdx.x * 64;

    // zero all 4 h buffers (contiguous 16384 floats at OFF_H0A)
    for (int i = tid; i < 16384; i += NT) sm[OFF_H0A + i] = 0.0f;
    load_weights(sm, eWih0, 2, eWhh0, ebih0, ebhh0, eWih1, eWhh1, ebih1, ebhh1, tid);
    if (tid < 64) outw[tid] = outW[tid];
    if (tid < 128) { // stage x for t=0
        int r = tid >> 1, c = tid & 1;
        xst[c * 64 + r] = x[((long)(rbase + r) * TIN) * 2 + c];
    }
    __syncthreads();

    u64 aR[2][4], aZ[2][4], nI[2][4], nH[2][4];
    int p = 0;

    // ===================== encoder =====================
    for (int t = 0; t < TIN; t++) {
        const float* h0s = sm + (p ? OFF_H0B : OFF_H0A);
        float*       h0d = sm + (p ? OFF_H0A : OFF_H0B);
        const float* h1s = sm + (p ? OFF_H1B : OFF_H1A);
        float*       h1d = sm + (p ? OFF_H1A : OFF_H1B);
        const float* xb  = xst + (t & 1) * 128;

        // layer0 init: bias + x @ Wih0^T (packed)
        {
            float4 x0v = *(const float4*)&xb[r0];
            float4 x1v = *(const float4*)&xb[64 + r0];
            u64 xd0[4] = {pack2(x0v.x, x0v.x), pack2(x0v.y, x0v.y), pack2(x0v.z, x0v.z), pack2(x0v.w, x0v.w)};
            u64 xd1[4] = {pack2(x1v.x, x1v.x), pack2(x1v.y, x1v.y), pack2(x1v.z, x1v.z), pack2(x1v.w, x1v.w)};
#pragma unroll
            for (int pp = 0; pp < 2; pp++) {
                int base = j0 + 2 * pp;
                u64 bR = *(const u64*)&b0[base];
                u64 bZ = *(const u64*)&b0[64 + base];
                u64 bI = *(const u64*)&b0[128 + base];
                u64 bH = *(const u64*)&b0[192 + base];
                u64 wR0 = *(const u64*)&w0s[base],        wR1 = *(const u64*)&w0s[192 + base];
                u64 wZ0 = *(const u64*)&w0s[64 + base],   wZ1 = *(const u64*)&w0s[192 + 64 + base];
                u64 wN0 = *(const u64*)&w0s[128 + base],  wN1 = *(const u64*)&w0s[192 + 128 + base];
#pragma unroll
                for (int ri = 0; ri < 4; ri++) {
                    aR[pp][ri] = fma2(xd1[ri], wR1, fma2(xd0[ri], wR0, bR));
                    aZ[pp][ri] = fma2(xd1[ri], wZ1, fma2(xd0[ri], wZ0, bZ));
                    nI[pp][ri] = fma2(xd1[ri], wN1, fma2(xd0[ri], wN0, bI));
                    nH[pp][ri] = bH;
                }
            }
        }
        kloop64p(h0s, wt0, aR, aZ, nH, r0, j0);        // hidden part -> r,z,n_hh
        gru_update2(h0s, h0d, aR, aZ, nI, nH, r0, j0);
        __syncthreads();

        // layer1: K=128 concat [h0_new ; h1_old]
        init_b(b1, aR, aZ, nI, nH, j0);
        kloop64p(h0d, wc1, aR, aZ, nI, r0, j0);             // ih part -> r,z,n_ih
        kloop64p(h1s, wc1 + 64 * 192, aR, aZ, nH, r0, j0);  // hh part -> r,z,n_hh
        gru_update2(h1s, h1d, aR, aZ, nI, nH, r0, j0);

        // stage x for t+1 (covered by the sync below)
        if (t + 1 < TIN && tid < 128) {
            int r = tid >> 1, c = tid & 1;
            xst[((t + 1) & 1) * 128 + c * 64 + r] = x[((long)(rbase + r) * TIN + (t + 1)) * 2 + c];
        }
        __syncthreads();
        p ^= 1;
    }

    // ===================== swap to decoder weights =====================
    load_weights(sm, dWih0, 1, dWhh0, dbih0, dbhh0, dWih1, dWhh1, dbih1, dbhh1, tid);
    if (tid < 64) prevb[tid] = 0.0f;
    __syncthreads();
    const float ob = outb[0];

    // ===================== decoder =====================
    for (int t = 0; t < TOUT; t++) {
        const float* h0s = sm + (p ? OFF_H0B : OFF_H0A);
        float*       h0d = sm + (p ? OFF_H0A : OFF_H0B);
        const float* h1s = sm + (p ? OFF_H1B : OFF_H1A);
        float*       h1d = sm + (p ? OFF_H1A : OFF_H1B);

        // layer0 init: bias + prev * Wih0 (nin=1)
        {
            float4 pv = *(const float4*)&prevb[r0];
            u64 pd[4] = {pack2(pv.x, pv.x), pack2(pv.y, pv.y), pack2(pv.z, pv.z), pack2(pv.w, pv.w)};
#pragma unroll
            for (int pp = 0; pp < 2; pp++) {
                int base = j0 + 2 * pp;
                u64 bR = *(const u64*)&b0[base];
                u64 bZ = *(const u64*)&b0[64 + base];
                u64 bI = *(const u64*)&b0[128 + base];
                u64 bH = *(const u64*)&b0[192 + base];
                u64 wR = *(const u64*)&w0s[base];
                u64 wZ = *(const u64*)&w0s[64 + base];
                u64 wN = *(const u64*)&w0s[128 + base];
#pragma unroll
                for (int ri = 0; ri < 4; ri++) {
                    aR[pp][ri] = fma2(pd[ri], wR, bR);
                    aZ[pp][ri] = fma2(pd[ri], wZ, bZ);
                    nI[pp][ri] = fma2(pd[ri], wN, bI);
                    nH[pp][ri] = bH;
                }
            }
        }
        kloop64p(h0s, wt0, aR, aZ, nH, r0, j0);
        gru_update2(h0s, h0d, aR, aZ, nI, nH, r0, j0);
        __syncthreads();

        init_b(b1, aR, aZ, nI, nH, j0);
        kloop64p(h0d, wc1, aR, aZ, nI, r0, j0);
        kloop64p(h1s, wc1 + 64 * 192, aR, aZ, nH, r0, j0);
        gru_update2(h1s, h1d, aR, aZ, nI, nH, r0, j0);
        __syncthreads();

        // output head: cv = h1_new @ outW^T + outb ; feed back as prev
        if (tid < 64) {
            float acc = ob;
#pragma unroll 8
            for (int j = 0; j < 64; j++) acc += h1d[j * 64 + tid] * outw[j];
            prevb[tid] = acc;
            out[(long)(rbase + tid) * TOUT + t] = acc;
        }
        __syncthreads();
        p ^= 1;
    }
}

extern "C" void kernel_launch(void* const* d_in, const int* in_sizes, int n_in,
                              void* d_out, int out_size) {
    const float* x     = (const float*)d_in[0];
    const float* eWih0 = (const float*)d_in[1];
    const float* eWhh0 = (const float*)d_in[2];
    const float* ebih0 = (const float*)d_in[3];
    const float* ebhh0 = (const float*)d_in[4];
    const float* eWih1 = (const float*)d_in[5];
    const float* eWhh1 = (const float*)d_in[6];
    const float* ebih1 = (const float*)d_in[7];
    const float* ebhh1 = (const float*)d_in[8];
    const float* dWih0 = (const float*)d_in[9];
    const float* dWhh0 = (const float*)d_in[10];
    const float* dbih0 = (const float*)d_in[11];
    const float* dbhh0 = (const float*)d_in[12];
    const float* dWih1 = (const float*)d_in[13];
    const float* dWhh1 = (const float*)d_in[14];
    const float* dbih1 = (const float*)d_in[15];
    const float* dbhh1 = (const float*)d_in[16];
    const float* outW  = (const float*)d_in[17];
    const float* outb  = (const float*)d_in[18];
    float* out = (float*)d_out;

    cudaFuncSetAttribute(gru_controller_kernel,
                         cudaFuncAttributeMaxDynamicSharedMemorySize, SMEM_BYTES);
    gru_controller_kernel<<<128, NT, SMEM_BYTES>>>(
        x, eWih0, eWhh0, ebih0, ebhh0, eWih1, eWhh1, ebih1, ebhh1,
        dWih0, dWhh0, dbih0, dbhh0, dWih1, dWhh1, dbih1, dbhh1,
        outW, outb, out);
}

// round 5
// speedup vs baseline: 2.2072x; 1.0353x over previous
#include <cuda_runtime.h>

// GRUController: B=8192, T_in=512, N_IN=2, H=64, T_out=180.
// Persistent per-CTA fp32 GRU, FFMA2 inner loops.
// R5: 512 threads (16 warps), 2 rows x 4 cols per thread, warp-uniform weight loads.

typedef unsigned long long u64;

#define TIN   512
#define TOUT  180
#define NT    512

// smem layout (float indices)
#define OFF_WT0   0        // 64*192   layer0 Whh^T [k][j]
#define OFF_WC1   12288    // 128*192  layer1 [Wih;Whh]^T
#define OFF_H0A   36864    // 64*64 h0 ping   [j][r]
#define OFF_H0B   40960
#define OFF_H1A   45056
#define OFF_H1B   49152
#define OFF_B0    53248    // 256: bR,bZ,bIN,bHN (layer0)
#define OFF_B1    53504    // 256
#define OFF_W0S   53760    // 384: layer0 ih weights transposed [c][g*64+j]
#define OFF_XST   54144    // 2 x 128 staged x, [c][r]
#define OFF_PREV  54400    // 64
#define OFF_OUTW  54464    // 64
#define SMEM_FLOATS 54528
#define SMEM_BYTES  (SMEM_FLOATS * 4)

__device__ __forceinline__ u64 pack2(float lo, float hi) {
    u64 r; asm("mov.b64 %0,{%1,%2};" : "=l"(r) : "f"(lo), "f"(hi)); return r;
}
__device__ __forceinline__ void unpack2(u64 v, float& lo, float& hi) {
    asm("mov.b64 {%0,%1},%2;" : "=f"(lo), "=f"(hi) : "l"(v));
}
__device__ __forceinline__ u64 fma2(u64 a, u64 b, u64 c) {
    u64 d; asm("fma.rn.f32x2 %0,%1,%2,%3;" : "=l"(d) : "l"(a), "l"(b), "l"(c)); return d;
}
__device__ __forceinline__ float tanh_t(float x) {
    float y; asm("tanh.approx.f32 %0,%1;" : "=f"(y) : "f"(x)); return y;
}
__device__ __forceinline__ float sigm_t(float x) {
    return fmaf(tanh_t(0.5f * x), 0.5f, 0.5f);
}

// Accumulators: a?[p][ri], p = column-pair (j0+2p, j0+2p+1), ri = row (r0+ri).
// lo half of each u64 = col j0+2p, hi half = col j0+2p+1.

__device__ __forceinline__ void kloop64p(const float* __restrict__ src,   // [k][r] 64x64
                                         const float* __restrict__ W,     // [k][192]
                                         u64 (&aR)[2][2], u64 (&aZ)[2][2], u64 (&aN)[2][2],
                                         int r0, int j0) {
#pragma unroll 4
    for (int k = 0; k < 64; k++) {
        float2 hv = *(const float2*)&src[k * 64 + r0];
        ulonglong2 wr = *(const ulonglong2*)&W[k * 192 + j0];          // warp-uniform
        ulonglong2 wz = *(const ulonglong2*)&W[k * 192 + 64 + j0];
        ulonglong2 wn = *(const ulonglong2*)&W[k * 192 + 128 + j0];
        u64 hd0 = pack2(hv.x, hv.x);
        u64 hd1 = pack2(hv.y, hv.y);
        aR[0][0] = fma2(hd0, wr.x, aR[0][0]);  aR[0][1] = fma2(hd1, wr.x, aR[0][1]);
        aR[1][0] = fma2(hd0, wr.y, aR[1][0]);  aR[1][1] = fma2(hd1, wr.y, aR[1][1]);
        aZ[0][0] = fma2(hd0, wz.x, aZ[0][0]);  aZ[0][1] = fma2(hd1, wz.x, aZ[0][1]);
        aZ[1][0] = fma2(hd0, wz.y, aZ[1][0]);  aZ[1][1] = fma2(hd1, wz.y, aZ[1][1]);
        aN[0][0] = fma2(hd0, wn.x, aN[0][0]);  aN[0][1] = fma2(hd1, wn.x, aN[0][1]);
        aN[1][0] = fma2(hd0, wn.y, aN[1][0]);  aN[1][1] = fma2(hd1, wn.y, aN[1][1]);
    }
}

__device__ __forceinline__ void init_b(const float* __restrict__ b,
                                       u64 (&aR)[2][2], u64 (&aZ)[2][2],
                                       u64 (&nI)[2][2], u64 (&nH)[2][2], int j0) {
#pragma unroll
    for (int p = 0; p < 2; p++) {
        int base = j0 + 2 * p;
        u64 bR = *(const u64*)&b[base];
        u64 bZ = *(const u64*)&b[64 + base];
        u64 bI = *(const u64*)&b[128 + base];
        u64 bH = *(const u64*)&b[192 + base];
#pragma unroll
        for (int ri = 0; ri < 2; ri++) { aR[p][ri] = bR; aZ[p][ri] = bZ; nI[p][ri] = bI; nH[p][ri] = bH; }
    }
}

// gates + state update; reads old h from hsrc, writes new h to hdst (no sync inside)
__device__ __forceinline__ void gru_update2(const float* __restrict__ hsrc, float* __restrict__ hdst,
                                            u64 (&aR)[2][2], u64 (&aZ)[2][2],
                                            u64 (&nI)[2][2], u64 (&nH)[2][2], int r0, int j0) {
#pragma unroll
    for (int p = 0; p < 2; p++) {
        int c0 = j0 + 2 * p, c1 = c0 + 1;
        float2 hA = *(const float2*)&hsrc[c0 * 64 + r0];   // col c0, rows r0,r0+1
        float2 hB = *(const float2*)&hsrc[c1 * 64 + r0];   // col c1
        float oA[2], oB[2];
        const float hAa[2] = {hA.x, hA.y};
        const float hBa[2] = {hB.x, hB.y};
#pragma unroll
        for (int ri = 0; ri < 2; ri++) {
            float arl, arh, azl, azh, nil, nih, nhl, nhh;
            unpack2(aR[p][ri], arl, arh);
            unpack2(aZ[p][ri], azl, azh);
            unpack2(nI[p][ri], nil, nih);
            unpack2(nH[p][ri], nhl, nhh);
            float rA = sigm_t(arl), rB = sigm_t(arh);
            float zA = sigm_t(azl), zB = sigm_t(azh);
            float nA = tanh_t(fmaf(rA, nhl, nil));
            float nB = tanh_t(fmaf(rB, nhh, nih));
            oA[ri] = fmaf(zA, hAa[ri] - nA, nA);
            oB[ri] = fmaf(zB, hBa[ri] - nB, nB);
        }
        *(float2*)&hdst[c0 * 64 + r0] = make_float2(oA[0], oA[1]);
        *(float2*)&hdst[c1 * 64 + r0] = make_float2(oB[0], oB[1]);
    }
}

__device__ void load_weights(float* __restrict__ sm,
                             const float* __restrict__ Wih0, int nin,
                             const float* __restrict__ Whh0,
                             const float* __restrict__ bih0, const float* __restrict__ bhh0,
                             const float* __restrict__ Wih1, const float* __restrict__ Whh1,
                             const float* __restrict__ bih1, const float* __restrict__ bhh1,
                             int tid) {
    float* wt0 = sm + OFF_WT0;
    float* wc1 = sm + OFF_WC1;
    float* b0  = sm + OFF_B0;
    float* b1  = sm + OFF_B1;
    float* w0s = sm + OFF_W0S;
    for (int i = tid; i < 12288; i += NT) { int j = i >> 6, k = i & 63; wt0[k * 192 + j] = Whh0[i]; }
    for (int i = tid; i < 12288; i += NT) { int j = i >> 6, k = i & 63; wc1[k * 192 + j] = Wih1[i]; }
    for (int i = tid; i < 12288; i += NT) { int j = i >> 6, k = i & 63; wc1[(64 + k) * 192 + j] = Whh1[i]; }
    // layer0 ih weights transposed: w0s[c*192 + g*64 + j] = Wih0[(g*64+j)*nin + c]
    for (int i = tid; i < 192 * nin; i += NT) { int c = i / 192, gj = i % 192; w0s[i] = Wih0[gj * nin + c]; }
    if (tid < 64) {
        b0[tid]       = bih0[tid]       + bhh0[tid];
        b0[64 + tid]  = bih0[64 + tid]  + bhh0[64 + tid];
        b0[128 + tid] = bih0[128 + tid];
        b0[192 + tid] = bhh0[128 + tid];
        b1[tid]       = bih1[tid]       + bhh1[tid];
        b1[64 + tid]  = bih1[64 + tid]  + bhh1[64 + tid];
        b1[128 + tid] = bih1[128 + tid];
        b1[192 + tid] = bhh1[128 + tid];
    }
}

extern "C" __global__ void __launch_bounds__(NT, 1)
gru_controller_kernel(const float* __restrict__ x,
                      const float* eWih0, const float* eWhh0, const float* ebih0, const float* ebhh0,
                      const float* eWih1, const float* eWhh1, const float* ebih1, const float* ebhh1,
                      const float* dWih0, const float* dWhh0, const float* dbih0, const float* dbhh0,
                      const float* dWih1, const float* dWhh1, const float* dbih1, const float* dbhh1,
                      const float* __restrict__ outW, const float* __restrict__ outb,
                      float* __restrict__ out) {
    extern __shared__ float sm[];
    float* wt0   = sm + OFF_WT0;
    float* wc1   = sm + OFF_WC1;
    float* b0    = sm + OFF_B0;
    float* b1    = sm + OFF_B1;
    float* w0s   = sm + OFF_W0S;
    float* xst   = sm + OFF_XST;
    float* prevb = sm + OFF_PREV;
    float* outw  = sm + OFF_OUTW;

    const int tid = threadIdx.x;
    const int rt = tid & 31, ct = tid >> 5;     // 32 row-groups x 16 col-groups
    const int r0 = rt * 2, j0 = ct * 4;         // 2 rows, 4 cols per thread
    const int rbase = blockIdx.x * 64;

    // zero all 4 h buffers (contiguous 16384 floats at OFF_H0A)
    for (int i = tid; i < 16384; i += NT) sm[OFF_H0A + i] = 0.0f;
    load_weights(sm, eWih0, 2, eWhh0, ebih0, ebhh0, eWih1, eWhh1, ebih1, ebhh1, tid);
    if (tid < 64) outw[tid] = outW[tid];
    if (tid < 128) { // stage x for t=0
        int r = tid >> 1, c = tid & 1;
        xst[c * 64 + r] = x[((long)(rbase + r) * TIN) * 2 + c];
    }
    __syncthreads();

    u64 aR[2][2], aZ[2][2], nI[2][2], nH[2][2];
    int p = 0;

    // ===================== encoder =====================
    for (int t = 0; t < TIN; t++) {
        const float* h0s = sm + (p ? OFF_H0B : OFF_H0A);
        float*       h0d = sm + (p ? OFF_H0A : OFF_H0B);
        const float* h1s = sm + (p ? OFF_H1B : OFF_H1A);
        float*       h1d = sm + (p ? OFF_H1A : OFF_H1B);
        const float* xb  = xst + (t & 1) * 128;

        // layer0 init: bias + x @ Wih0^T
        {
            float2 x0v = *(const float2*)&xb[r0];
            float2 x1v = *(const float2*)&xb[64 + r0];
            u64 xd00 = pack2(x0v.x, x0v.x), xd01 = pack2(x0v.y, x0v.y);
            u64 xd10 = pack2(x1v.x, x1v.x), xd11 = pack2(x1v.y, x1v.y);
#pragma unroll
            for (int pp = 0; pp < 2; pp++) {
                int base = j0 + 2 * pp;
                u64 bR = *(const u64*)&b0[base];
                u64 bZ = *(const u64*)&b0[64 + base];
                u64 bI = *(const u64*)&b0[128 + base];
                u64 bH = *(const u64*)&b0[192 + base];
                u64 wR0 = *(const u64*)&w0s[base],        wR1 = *(const u64*)&w0s[192 + base];
                u64 wZ0 = *(const u64*)&w0s[64 + base],   wZ1 = *(const u64*)&w0s[192 + 64 + base];
                u64 wN0 = *(const u64*)&w0s[128 + base],  wN1 = *(const u64*)&w0s[192 + 128 + base];
                aR[pp][0] = fma2(xd10, wR1, fma2(xd00, wR0, bR));
                aR[pp][1] = fma2(xd11, wR1, fma2(xd01, wR0, bR));
                aZ[pp][0] = fma2(xd10, wZ1, fma2(xd00, wZ0, bZ));
                aZ[pp][1] = fma2(xd11, wZ1, fma2(xd01, wZ0, bZ));
                nI[pp][0] = fma2(xd10, wN1, fma2(xd00, wN0, bI));
                nI[pp][1] = fma2(xd11, wN1, fma2(xd01, wN0, bI));
                nH[pp][0] = bH;
                nH[pp][1] = bH;
            }
        }
        kloop64p(h0s, wt0, aR, aZ, nH, r0, j0);        // hidden part -> r,z,n_hh
        gru_update2(h0s, h0d, aR, aZ, nI, nH, r0, j0);
        __syncthreads();

        // layer1: K=128 concat [h0_new ; h1_old]
        init_b(b1, aR, aZ, nI, nH, j0);
        kloop64p(h0d, wc1, aR, aZ, nI, r0, j0);             // ih part -> r,z,n_ih
        kloop64p(h1s, wc1 + 64 * 192, aR, aZ, nH, r0, j0);  // hh part -> r,z,n_hh
        gru_update2(h1s, h1d, aR, aZ, nI, nH, r0, j0);

        // stage x for t+1 (covered by the sync below)
        if (t + 1 < TIN && tid < 128) {
            int r = tid >> 1, c = tid & 1;
            xst[((t + 1) & 1) * 128 + c * 64 + r] = x[((long)(rbase + r) * TIN + (t + 1)) * 2 + c];
        }
        __syncthreads();
        p ^= 1;
    }

    // ===================== swap to decoder weights =====================
    load_weights(sm, dWih0, 1, dWhh0, dbih0, dbhh0, dWih1, dWhh1, dbih1, dbhh1, tid);
    if (tid < 64) prevb[tid] = 0.0f;
    __syncthreads();
    const float ob = outb[0];

    // ===================== decoder =====================
    for (int t = 0; t < TOUT; t++) {
        const float* h0s = sm + (p ? OFF_H0B : OFF_H0A);
        float*       h0d = sm + (p ? OFF_H0A : OFF_H0B);
        const float* h1s = sm + (p ? OFF_H1B : OFF_H1A);
        float*       h1d = sm + (p ? OFF_H1A : OFF_H1B);

        // layer0 init: bias + prev * Wih0 (nin=1)
        {
            float2 pv = *(const float2*)&prevb[r0];
            u64 pd0 = pack2(pv.x, pv.x), pd1 = pack2(pv.y, pv.y);
#pragma unroll
            for (int pp = 0; pp < 2; pp++) {
                int base = j0 + 2 * pp;
                u64 bR = *(const u64*)&b0[base];
                u64 bZ = *(const u64*)&b0[64 + base];
                u64 bI = *(const u64*)&b0[128 + base];
                u64 bH = *(const u64*)&b0[192 + base];
                u64 wR = *(const u64*)&w0s[base];
                u64 wZ = *(const u64*)&w0s[64 + base];
                u64 wN = *(const u64*)&w0s[128 + base];
                aR[pp][0] = fma2(pd0, wR, bR);
                aR[pp][1] = fma2(pd1, wR, bR);
                aZ[pp][0] = fma2(pd0, wZ, bZ);
                aZ[pp][1] = fma2(pd1, wZ, bZ);
                nI[pp][0] = fma2(pd0, wN, bI);
                nI[pp][1] = fma2(pd1, wN, bI);
                nH[pp][0] = bH;
                nH[pp][1] = bH;
            }
        }
        kloop64p(h0s, wt0, aR, aZ, nH, r0, j0);
        gru_update2(h0s, h0d, aR, aZ, nI, nH, r0, j0);
        __syncthreads();

        init_b(b1, aR, aZ, nI, nH, j0);
        kloop64p(h0d, wc1, aR, aZ, nI, r0, j0);
        kloop64p(h1s, wc1 + 64 * 192, aR, aZ, nH, r0, j0);
        gru_update2(h1s, h1d, aR, aZ, nI, nH, r0, j0);
        __syncthreads();

        // output head: cv = h1_new @ outW^T + outb ; feed back as prev
        if (tid < 64) {
            float acc = ob;
#pragma unroll 8
            for (int j = 0; j < 64; j++) acc += h1d[j * 64 + tid] * outw[j];
            prevb[tid] = acc;
            out[(long)(rbase + tid) * TOUT + t] = acc;
        }
        __syncthreads();
        p ^= 1;
    }
}

extern "C" void kernel_launch(void* const* d_in, const int* in_sizes, int n_in,
                              void* d_out, int out_size) {
    const float* x     = (const float*)d_in[0];
    const float* eWih0 = (const float*)d_in[1];
    const float* eWhh0 = (const float*)d_in[2];
    const float* ebih0 = (const float*)d_in[3];
    const float* ebhh0 = (const float*)d_in[4];
    const float* eWih1 = (const float*)d_in[5];
    const float* eWhh1 = (const float*)d_in[6];
    const float* ebih1 = (const float*)d_in[7];
    const float* ebhh1 = (const float*)d_in[8];
    const float* dWih0 = (const float*)d_in[9];
    const float* dWhh0 = (const float*)d_in[10];
    const float* dbih0 = (const float*)d_in[11];
    const float* dbhh0 = (const float*)d_in[12];
    const float* dWih1 = (const float*)d_in[13];
    const float* dWhh1 = (const float*)d_in[14];
    const float* dbih1 = (const float*)d_in[15];
    const float* dbhh1 = (const float*)d_in[16];
    const float* outW  = (const float*)d_in[17];
    const float* outb  = (const float*)d_in[18];
    float* out = (float*)d_out;

    cudaFuncSetAttribute(gru_controller_kernel,
                         cudaFuncAttributeMaxDynamicSharedMemorySize, SMEM_BYTES);
    gru_controller_kernel<<<128, NT, SMEM_BYTES>>>(
        x, eWih0, eWhh0, ebih0, ebhh0, eWih1, eWhh1, ebih1, ebhh1,
        dWih0, dWhh0, dbih0, dbhh0, dWih1, dWhh1, dbih1, dbhh1,
        outW, outb, out);
}

// round 6
// speedup vs baseline: 2.2328x; 1.0116x over previous
#include <cuda_runtime.h>

// GRUController: B=8192, T_in=512, N_IN=2, H=64, T_out=180.
// Persistent per-CTA fp32 GRU, FFMA2 inner loops.
// R6: 1 barrier/step encoder, merged layer-1 contraction, parallel decoder head.

typedef unsigned long long u64;

#define TIN   512
#define TOUT  180
#define NT    512

// smem layout (float indices)
#define OFF_WT0   0        // 64*192   layer0 Whh^T [k][j]
#define OFF_WC1   12288    // 128*192  layer1 [Wih;Whh]^T
#define OFF_H0A   36864    // 64*64 h0 ping   [j][r]
#define OFF_H0B   40960
#define OFF_H1A   45056
#define OFF_H1B   49152
#define OFF_B0    53248    // 256: bR,bZ,bIN,bHN (layer0)
#define OFF_B1    53504    // 256
#define OFF_W0S   53760    // 384: layer0 ih weights transposed [c][g*64+j]
#define OFF_XST   54144    // 2 x 128 staged x, [c][r]
#define OFF_PREV  54400    // 64
#define OFF_OUTW  54464    // 64
#define OFF_PART  54528    // 16*64 decoder head partials [ct][r]
#define SMEM_FLOATS 55552
#define SMEM_BYTES  (SMEM_FLOATS * 4)   // 222,208 B

__device__ __forceinline__ u64 pack2(float lo, float hi) {
    u64 r; asm("mov.b64 %0,{%1,%2};" : "=l"(r) : "f"(lo), "f"(hi)); return r;
}
__device__ __forceinline__ void unpack2(u64 v, float& lo, float& hi) {
    asm("mov.b64 {%0,%1},%2;" : "=f"(lo), "=f"(hi) : "l"(v));
}
__device__ __forceinline__ u64 fma2(u64 a, u64 b, u64 c) {
    u64 d; asm("fma.rn.f32x2 %0,%1,%2,%3;" : "=l"(d) : "l"(a), "l"(b), "l"(c)); return d;
}
__device__ __forceinline__ float tanh_t(float x) {
    float y; asm("tanh.approx.f32 %0,%1;" : "=f"(y) : "f"(x)); return y;
}
__device__ __forceinline__ float sigm_t(float x) {
    return fmaf(tanh_t(0.5f * x), 0.5f, 0.5f);
}

// Accumulators: a?[p][ri], p = column-pair (j0+2p, j0+2p+1), ri = row (r0+ri).

__device__ __forceinline__ void kloop64p(const float* __restrict__ src,   // [k][r] 64x64
                                         const float* __restrict__ W,     // [k][192]
                                         u64 (&aR)[2][2], u64 (&aZ)[2][2], u64 (&aN)[2][2],
                                         int r0, int j0) {
#pragma unroll 4
    for (int k = 0; k < 64; k++) {
        float2 hv = *(const float2*)&src[k * 64 + r0];
        ulonglong2 wr = *(const ulonglong2*)&W[k * 192 + j0];          // warp-uniform
        ulonglong2 wz = *(const ulonglong2*)&W[k * 192 + 64 + j0];
        ulonglong2 wn = *(const ulonglong2*)&W[k * 192 + 128 + j0];
        u64 hd0 = pack2(hv.x, hv.x);
        u64 hd1 = pack2(hv.y, hv.y);
        aR[0][0] = fma2(hd0, wr.x, aR[0][0]);  aR[0][1] = fma2(hd1, wr.x, aR[0][1]);
        aR[1][0] = fma2(hd0, wr.y, aR[1][0]);  aR[1][1] = fma2(hd1, wr.y, aR[1][1]);
        aZ[0][0] = fma2(hd0, wz.x, aZ[0][0]);  aZ[0][1] = fma2(hd1, wz.x, aZ[0][1]);
        aZ[1][0] = fma2(hd0, wz.y, aZ[1][0]);  aZ[1][1] = fma2(hd1, wz.y, aZ[1][1]);
        aN[0][0] = fma2(hd0, wn.x, aN[0][0]);  aN[0][1] = fma2(hd1, wn.x, aN[0][1]);
        aN[1][0] = fma2(hd0, wn.y, aN[1][0]);  aN[1][1] = fma2(hd1, wn.y, aN[1][1]);
    }
}

// merged layer-1 contraction: ih part over h0 (-> nI) + hh part over h1 (-> nH),
// r,z get both contributions. W rows: k = ih, 64+k = hh.
__device__ __forceinline__ void kloop_l1(const float* __restrict__ h0,
                                         const float* __restrict__ h1,
                                         const float* __restrict__ W,     // [128][192]
                                         u64 (&aR)[2][2], u64 (&aZ)[2][2],
                                         u64 (&nI)[2][2], u64 (&nH)[2][2],
                                         int r0, int j0) {
#pragma unroll 2
    for (int k = 0; k < 64; k++) {
        float2 ha = *(const float2*)&h0[k * 64 + r0];
        float2 hb = *(const float2*)&h1[k * 64 + r0];
        ulonglong2 wrA = *(const ulonglong2*)&W[k * 192 + j0];
        ulonglong2 wzA = *(const ulonglong2*)&W[k * 192 + 64 + j0];
        ulonglong2 wnA = *(const ulonglong2*)&W[k * 192 + 128 + j0];
        ulonglong2 wrB = *(const ulonglong2*)&W[(64 + k) * 192 + j0];
        ulonglong2 wzB = *(const ulonglong2*)&W[(64 + k) * 192 + 64 + j0];
        ulonglong2 wnB = *(const ulonglong2*)&W[(64 + k) * 192 + 128 + j0];
        u64 ha0 = pack2(ha.x, ha.x), ha1 = pack2(ha.y, ha.y);
        u64 hb0 = pack2(hb.x, hb.x), hb1 = pack2(hb.y, hb.y);
        aR[0][0] = fma2(ha0, wrA.x, aR[0][0]);  aR[0][1] = fma2(ha1, wrA.x, aR[0][1]);
        aR[1][0] = fma2(ha0, wrA.y, aR[1][0]);  aR[1][1] = fma2(ha1, wrA.y, aR[1][1]);
        aZ[0][0] = fma2(ha0, wzA.x, aZ[0][0]);  aZ[0][1] = fma2(ha1, wzA.x, aZ[0][1]);
        aZ[1][0] = fma2(ha0, wzA.y, aZ[1][0]);  aZ[1][1] = fma2(ha1, wzA.y, aZ[1][1]);
        nI[0][0] = fma2(ha0, wnA.x, nI[0][0]);  nI[0][1] = fma2(ha1, wnA.x, nI[0][1]);
        nI[1][0] = fma2(ha0, wnA.y, nI[1][0]);  nI[1][1] = fma2(ha1, wnA.y, nI[1][1]);
        aR[0][0] = fma2(hb0, wrB.x, aR[0][0]);  aR[0][1] = fma2(hb1, wrB.x, aR[0][1]);
        aR[1][0] = fma2(hb0, wrB.y, aR[1][0]);  aR[1][1] = fma2(hb1, wrB.y, aR[1][1]);
        aZ[0][0] = fma2(hb0, wzB.x, aZ[0][0]);  aZ[0][1] = fma2(hb1, wzB.x, aZ[0][1]);
        aZ[1][0] = fma2(hb0, wzB.y, aZ[1][0]);  aZ[1][1] = fma2(hb1, wzB.y, aZ[1][1]);
        nH[0][0] = fma2(hb0, wnB.x, nH[0][0]);  nH[0][1] = fma2(hb1, wnB.x, nH[0][1]);
        nH[1][0] = fma2(hb0, wnB.y, nH[1][0]);  nH[1][1] = fma2(hb1, wnB.y, nH[1][1]);
    }
}

__device__ __forceinline__ void init_b(const float* __restrict__ b,
                                       u64 (&aR)[2][2], u64 (&aZ)[2][2],
                                       u64 (&nI)[2][2], u64 (&nH)[2][2], int j0) {
#pragma unroll
    for (int p = 0; p < 2; p++) {
        int base = j0 + 2 * p;
        u64 bR = *(const u64*)&b[base];
        u64 bZ = *(const u64*)&b[64 + base];
        u64 bI = *(const u64*)&b[128 + base];
        u64 bH = *(const u64*)&b[192 + base];
#pragma unroll
        for (int ri = 0; ri < 2; ri++) { aR[p][ri] = bR; aZ[p][ri] = bZ; nI[p][ri] = bI; nH[p][ri] = bH; }
    }
}

// gates + state update; optionally also emits decoder-head partials.
template <bool HEAD>
__device__ __forceinline__ void gru_update2(const float* __restrict__ hsrc, float* __restrict__ hdst,
                                            u64 (&aR)[2][2], u64 (&aZ)[2][2],
                                            u64 (&nI)[2][2], u64 (&nH)[2][2],
                                            int r0, int j0,
                                            const float* wo, float* partrow) {
    float part[2] = {0.0f, 0.0f};
#pragma unroll
    for (int p = 0; p < 2; p++) {
        int c0 = j0 + 2 * p, c1 = c0 + 1;
        float2 hA = *(const float2*)&hsrc[c0 * 64 + r0];
        float2 hB = *(const float2*)&hsrc[c1 * 64 + r0];
        float oA[2], oB[2];
        const float hAa[2] = {hA.x, hA.y};
        const float hBa[2] = {hB.x, hB.y};
#pragma unroll
        for (int ri = 0; ri < 2; ri++) {
            float arl, arh, azl, azh, nil, nih, nhl, nhh;
            unpack2(aR[p][ri], arl, arh);
            unpack2(aZ[p][ri], azl, azh);
            unpack2(nI[p][ri], nil, nih);
            unpack2(nH[p][ri], nhl, nhh);
            float rA = sigm_t(arl), rB = sigm_t(arh);
            float zA = sigm_t(azl), zB = sigm_t(azh);
            float nA = tanh_t(fmaf(rA, nhl, nil));
            float nB = tanh_t(fmaf(rB, nhh, nih));
            oA[ri] = fmaf(zA, hAa[ri] - nA, nA);
            oB[ri] = fmaf(zB, hBa[ri] - nB, nB);
            if (HEAD) part[ri] = fmaf(oA[ri], wo[2 * p], fmaf(oB[ri], wo[2 * p + 1], part[ri]));
        }
        *(float2*)&hdst[c0 * 64 + r0] = make_float2(oA[0], oA[1]);
        *(float2*)&hdst[c1 * 64 + r0] = make_float2(oB[0], oB[1]);
    }
    if (HEAD) *(float2*)&partrow[r0] = make_float2(part[0], part[1]);
}

__device__ void load_weights(float* __restrict__ sm,
                             const float* __restrict__ Wih0, int nin,
                             const float* __restrict__ Whh0,
                             const float* __restrict__ bih0, const float* __restrict__ bhh0,
                             const float* __restrict__ Wih1, const float* __restrict__ Whh1,
                             const float* __restrict__ bih1, const float* __restrict__ bhh1,
                             int tid) {
    float* wt0 = sm + OFF_WT0;
    float* wc1 = sm + OFF_WC1;
    float* b0  = sm + OFF_B0;
    float* b1  = sm + OFF_B1;
    float* w0s = sm + OFF_W0S;
    for (int i = tid; i < 12288; i += NT) { int j = i >> 6, k = i & 63; wt0[k * 192 + j] = Whh0[i]; }
    for (int i = tid; i < 12288; i += NT) { int j = i >> 6, k = i & 63; wc1[k * 192 + j] = Wih1[i]; }
    for (int i = tid; i < 12288; i += NT) { int j = i >> 6, k = i & 63; wc1[(64 + k) * 192 + j] = Whh1[i]; }
    for (int i = tid; i < 192 * nin; i += NT) { int c = i / 192, gj = i % 192; w0s[i] = Wih0[gj * nin + c]; }
    if (tid < 64) {
        b0[tid]       = bih0[tid]       + bhh0[tid];
        b0[64 + tid]  = bih0[64 + tid]  + bhh0[64 + tid];
        b0[128 + tid] = bih0[128 + tid];
        b0[192 + tid] = bhh0[128 + tid];
        b1[tid]       = bih1[tid]       + bhh1[tid];
        b1[64 + tid]  = bih1[64 + tid]  + bhh1[64 + tid];
        b1[128 + tid] = bih1[128 + tid];
        b1[192 + tid] = bhh1[128 + tid];
    }
}

extern "C" __global__ void __launch_bounds__(NT, 1)
gru_controller_kernel(const float* __restrict__ x,
                      const float* eWih0, const float* eWhh0, const float* ebih0, const float* ebhh0,
                      const float* eWih1, const float* eWhh1, const float* ebih1, const float* ebhh1,
                      const float* dWih0, const float* dWhh0, const float* dbih0, const float* dbhh0,
                      const float* dWih1, const float* dWhh1, const float* dbih1, const float* dbhh1,
                      const float* __restrict__ outW, const float* __restrict__ outb,
                      float* __restrict__ out) {
    extern __shared__ float sm[];
    float* wt0   = sm + OFF_WT0;
    float* wc1   = sm + OFF_WC1;
    float* b0    = sm + OFF_B0;
    float* b1    = sm + OFF_B1;
    float* w0s   = sm + OFF_W0S;
    float* xst   = sm + OFF_XST;
    float* prevb = sm + OFF_PREV;
    float* outw  = sm + OFF_OUTW;
    float* partb = sm + OFF_PART;

    const int tid = threadIdx.x;
    const int rt = tid & 31, ct = tid >> 5;     // 32 row-groups x 16 warps
    const int r0 = rt * 2, j0 = ct * 4;         // 2 rows, 4 cols per thread
    const int rbase = blockIdx.x * 64;

    for (int i = tid; i < 16384; i += NT) sm[OFF_H0A + i] = 0.0f;
    load_weights(sm, eWih0, 2, eWhh0, ebih0, ebhh0, eWih1, eWhh1, ebih1, ebhh1, tid);
    if (tid < 64) outw[tid] = outW[tid];
    if (tid < 128) { // stage x for t=0
        int r = tid >> 1, c = tid & 1;
        xst[c * 64 + r] = x[((long)(rbase + r) * TIN) * 2 + c];
    }
    __syncthreads();

    u64 aR[2][2], aZ[2][2], nI[2][2], nH[2][2];
    int p = 0;

    // ===================== encoder (1 barrier/step) =====================
    for (int t = 0; t < TIN; t++) {
        const float* h0s = sm + (p ? OFF_H0B : OFF_H0A);
        float*       h0d = sm + (p ? OFF_H0A : OFF_H0B);
        const float* h1s = sm + (p ? OFF_H1B : OFF_H1A);
        float*       h1d = sm + (p ? OFF_H1A : OFF_H1B);
        const float* xb  = xst + (t & 1) * 128;

        // stage x for t+1 into the OTHER slot (read slot is t&1; no conflict)
        if (t + 1 < TIN && tid < 128) {
            int r = tid >> 1, c = tid & 1;
            xst[((t + 1) & 1) * 128 + c * 64 + r] = x[((long)(rbase + r) * TIN + (t + 1)) * 2 + c];
        }

        // layer0 init: bias + x @ Wih0^T
        {
            float2 x0v = *(const float2*)&xb[r0];
            float2 x1v = *(const float2*)&xb[64 + r0];
            u64 xd00 = pack2(x0v.x, x0v.x), xd01 = pack2(x0v.y, x0v.y);
            u64 xd10 = pack2(x1v.x, x1v.x), xd11 = pack2(x1v.y, x1v.y);
#pragma unroll
            for (int pp = 0; pp < 2; pp++) {
                int base = j0 + 2 * pp;
                u64 bR = *(const u64*)&b0[base];
                u64 bZ = *(const u64*)&b0[64 + base];
                u64 bI = *(const u64*)&b0[128 + base];
                u64 bH = *(const u64*)&b0[192 + base];
                u64 wR0 = *(const u64*)&w0s[base],        wR1 = *(const u64*)&w0s[192 + base];
                u64 wZ0 = *(const u64*)&w0s[64 + base],   wZ1 = *(const u64*)&w0s[192 + 64 + base];
                u64 wN0 = *(const u64*)&w0s[128 + base],  wN1 = *(const u64*)&w0s[192 + 128 + base];
                aR[pp][0] = fma2(xd10, wR1, fma2(xd00, wR0, bR));
                aR[pp][1] = fma2(xd11, wR1, fma2(xd01, wR0, bR));
                aZ[pp][0] = fma2(xd10, wZ1, fma2(xd00, wZ0, bZ));
                aZ[pp][1] = fma2(xd11, wZ1, fma2(xd01, wZ0, bZ));
                nI[pp][0] = fma2(xd10, wN1, fma2(xd00, wN0, bI));
                nI[pp][1] = fma2(xd11, wN1, fma2(xd01, wN0, bI));
                nH[pp][0] = bH;
                nH[pp][1] = bH;
            }
        }
        kloop64p(h0s, wt0, aR, aZ, nH, r0, j0);
        gru_update2<false>(h0s, h0d, aR, aZ, nI, nH, r0, j0, 0, 0);
        __syncthreads();   // the ONE barrier: layer0-write -> layer1-read

        init_b(b1, aR, aZ, nI, nH, j0);
        kloop_l1(h0d, h1s, wc1, aR, aZ, nI, nH, r0, j0);
        gru_update2<false>(h1s, h1d, aR, aZ, nI, nH, r0, j0, 0, 0);
        // no trailing barrier: all step-t+1 pre-sync reads are of data sealed
        // before this step's barrier (see R6 hazard analysis)
        p ^= 1;
    }

    // ===================== swap to decoder weights =====================
    __syncthreads();   // encoder warps may still be reading wt0/wc1
    load_weights(sm, dWih0, 1, dWhh0, dbih0, dbhh0, dWih1, dWhh1, dbih1, dbhh1, tid);
    if (tid < 64) prevb[tid] = 0.0f;
    __syncthreads();
    const float ob = outb[0];
    float wo[4];
#pragma unroll
    for (int c = 0; c < 4; c++) wo[c] = outw[j0 + c];   // warp-uniform broadcast

    // ===================== decoder =====================
    for (int t = 0; t < TOUT; t++) {
        const float* h0s = sm + (p ? OFF_H0B : OFF_H0A);
        float*       h0d = sm + (p ? OFF_H0A : OFF_H0B);
        const float* h1s = sm + (p ? OFF_H1B : OFF_H1A);
        float*       h1d = sm + (p ? OFF_H1A : OFF_H1B);

        // layer0 init: bias + prev * Wih0 (nin=1)
        {
            float2 pv = *(const float2*)&prevb[r0];
            u64 pd0 = pack2(pv.x, pv.x), pd1 = pack2(pv.y, pv.y);
#pragma unroll
            for (int pp = 0; pp < 2; pp++) {
                int base = j0 + 2 * pp;
                u64 bR = *(const u64*)&b0[base];
                u64 bZ = *(const u64*)&b0[64 + base];
                u64 bI = *(const u64*)&b0[128 + base];
                u64 bH = *(const u64*)&b0[192 + base];
                u64 wR = *(const u64*)&w0s[base];
                u64 wZ = *(const u64*)&w0s[64 + base];
                u64 wN = *(const u64*)&w0s[128 + base];
                aR[pp][0] = fma2(pd0, wR, bR);
                aR[pp][1] = fma2(pd1, wR, bR);
                aZ[pp][0] = fma2(pd0, wZ, bZ);
                aZ[pp][1] = fma2(pd1, wZ, bZ);
                nI[pp][0] = fma2(pd0, wN, bI);
                nI[pp][1] = fma2(pd1, wN, bI);
                nH[pp][0] = bH;
                nH[pp][1] = bH;
            }
        }
        kloop64p(h0s, wt0, aR, aZ, nH, r0, j0);
        gru_update2<false>(h0s, h0d, aR, aZ, nI, nH, r0, j0, 0, 0);
        __syncthreads();

        init_b(b1, aR, aZ, nI, nH, j0);
        kloop_l1(h0d, h1s, wc1, aR, aZ, nI, nH, r0, j0);
        gru_update2<true>(h1s, h1d, aR, aZ, nI, nH, r0, j0, wo, partb + ct * 64);
        __syncthreads();

        // head reduce: out[r] = ob + sum_ct part[ct][r]
        if (tid < 64) {
            float acc = ob;
#pragma unroll
            for (int c = 0; c < 16; c++) acc += partb[c * 64 + tid];
            prevb[tid] = acc;
            out[(long)(rbase + tid) * TOUT + t] = acc;
        }
        __syncthreads();
        p ^= 1;
    }
}

extern "C" void kernel_launch(void* const* d_in, const int* in_sizes, int n_in,
                              void* d_out, int out_size) {
    const float* x     = (const float*)d_in[0];
    const float* eWih0 = (const float*)d_in[1];
    const float* eWhh0 = (const float*)d_in[2];
    const float* ebih0 = (const float*)d_in[3];
    const float* ebhh0 = (const float*)d_in[4];
    const float* eWih1 = (const float*)d_in[5];
    const float* eWhh1 = (const float*)d_in[6];
    const float* ebih1 = (const float*)d_in[7];
    const float* ebhh1 = (const float*)d_in[8];
    const float* dWih0 = (const float*)d_in[9];
    const float* dWhh0 = (const float*)d_in[10];
    const float* dbih0 = (const float*)d_in[11];
    const float* dbhh0 = (const float*)d_in[12];
    const float* dWih1 = (const float*)d_in[13];
    const float* dWhh1 = (const float*)d_in[14];
    const float* dbih1 = (const float*)d_in[15];
    const float* dbhh1 = (const float*)d_in[16];
    const float* outW  = (const float*)d_in[17];
    const float* outb  = (const float*)d_in[18];
    float* out = (float*)d_out;

    cudaFuncSetAttribute(gru_controller_kernel,
                         cudaFuncAttributeMaxDynamicSharedMemorySize, SMEM_BYTES);
    gru_controller_kernel<<<128, NT, SMEM_BYTES>>>(
        x, eWih0, eWhh0, ebih0, ebhh0, eWih1, eWhh1, ebih1, ebhh1,
        dWih0, dWhh0, dbih0, dbhh0, dWih1, dWhh1, dbih1, dbhh1,
        outW, outb, out);
}

// round 7
// speedup vs baseline: 2.2361x; 1.0015x over previous
#include <cuda_runtime.h>

// GRUController: B=8192, T_in=512, N_IN=2, H=64, T_out=180.
// Persistent per-CTA fp32 GRU, FFMA2 inner loops.
// R6: 1 barrier/step encoder, merged layer-1 contraction, parallel decoder head.

typedef unsigned long long u64;

#define TIN   512
#define TOUT  180
#define NT    512

// smem layout (float indices)
#define OFF_WT0   0        // 64*192   layer0 Whh^T [k][j]
#define OFF_WC1   12288    // 128*192  layer1 [Wih;Whh]^T
#define OFF_H0A   36864    // 64*64 h0 ping   [j][r]
#define OFF_H0B   40960
#define OFF_H1A   45056
#define OFF_H1B   49152
#define OFF_B0    53248    // 256: bR,bZ,bIN,bHN (layer0)
#define OFF_B1    53504    // 256
#define OFF_W0S   53760    // 384: layer0 ih weights transposed [c][g*64+j]
#define OFF_XST   54144    // 2 x 128 staged x, [c][r]
#define OFF_PREV  54400    // 64
#define OFF_OUTW  54464    // 64
#define OFF_PART  54528    // 16*64 decoder head partials [ct][r]
#define SMEM_FLOATS 55552
#define SMEM_BYTES  (SMEM_FLOATS * 4)   // 222,208 B

__device__ __forceinline__ u64 pack2(float lo, float hi) {
    u64 r; asm("mov.b64 %0,{%1,%2};" : "=l"(r) : "f"(lo), "f"(hi)); return r;
}
__device__ __forceinline__ void unpack2(u64 v, float& lo, float& hi) {
    asm("mov.b64 {%0,%1},%2;" : "=f"(lo), "=f"(hi) : "l"(v));
}
__device__ __forceinline__ u64 fma2(u64 a, u64 b, u64 c) {
    u64 d; asm("fma.rn.f32x2 %0,%1,%2,%3;" : "=l"(d) : "l"(a), "l"(b), "l"(c)); return d;
}
__device__ __forceinline__ float tanh_t(float x) {
    float y; asm("tanh.approx.f32 %0,%1;" : "=f"(y) : "f"(x)); return y;
}
__device__ __forceinline__ float sigm_t(float x) {
    return fmaf(tanh_t(0.5f * x), 0.5f, 0.5f);
}

// Accumulators: a?[p][ri], p = column-pair (j0+2p, j0+2p+1), ri = row (r0+ri).

__device__ __forceinline__ void kloop64p(const float* __restrict__ src,   // [k][r] 64x64
                                         const float* __restrict__ W,     // [k][192]
                                         u64 (&aR)[2][2], u64 (&aZ)[2][2], u64 (&aN)[2][2],
                                         int r0, int j0) {
#pragma unroll 4
    for (int k = 0; k < 64; k++) {
        float2 hv = *(const float2*)&src[k * 64 + r0];
        ulonglong2 wr = *(const ulonglong2*)&W[k * 192 + j0];          // warp-uniform
        ulonglong2 wz = *(const ulonglong2*)&W[k * 192 + 64 + j0];
        ulonglong2 wn = *(const ulonglong2*)&W[k * 192 + 128 + j0];
        u64 hd0 = pack2(hv.x, hv.x);
        u64 hd1 = pack2(hv.y, hv.y);
        aR[0][0] = fma2(hd0, wr.x, aR[0][0]);  aR[0][1] = fma2(hd1, wr.x, aR[0][1]);
        aR[1][0] = fma2(hd0, wr.y, aR[1][0]);  aR[1][1] = fma2(hd1, wr.y, aR[1][1]);
        aZ[0][0] = fma2(hd0, wz.x, aZ[0][0]);  aZ[0][1] = fma2(hd1, wz.x, aZ[0][1]);
        aZ[1][0] = fma2(hd0, wz.y, aZ[1][0]);  aZ[1][1] = fma2(hd1, wz.y, aZ[1][1]);
        aN[0][0] = fma2(hd0, wn.x, aN[0][0]);  aN[0][1] = fma2(hd1, wn.x, aN[0][1]);
        aN[1][0] = fma2(hd0, wn.y, aN[1][0]);  aN[1][1] = fma2(hd1, wn.y, aN[1][1]);
    }
}

// merged layer-1 contraction: ih part over h0 (-> nI) + hh part over h1 (-> nH),
// r,z get both contributions. W rows: k = ih, 64+k = hh.
__device__ __forceinline__ void kloop_l1(const float* __restrict__ h0,
                                         const float* __restrict__ h1,
                                         const float* __restrict__ W,     // [128][192]
                                         u64 (&aR)[2][2], u64 (&aZ)[2][2],
                                         u64 (&nI)[2][2], u64 (&nH)[2][2],
                                         int r0, int j0) {
#pragma unroll 2
    for (int k = 0; k < 64; k++) {
        float2 ha = *(const float2*)&h0[k * 64 + r0];
        float2 hb = *(const float2*)&h1[k * 64 + r0];
        ulonglong2 wrA = *(const ulonglong2*)&W[k * 192 + j0];
        ulonglong2 wzA = *(const ulonglong2*)&W[k * 192 + 64 + j0];
        ulonglong2 wnA = *(const ulonglong2*)&W[k * 192 + 128 + j0];
        ulonglong2 wrB = *(const ulonglong2*)&W[(64 + k) * 192 + j0];
        ulonglong2 wzB = *(const ulonglong2*)&W[(64 + k) * 192 + 64 + j0];
        ulonglong2 wnB = *(const ulonglong2*)&W[(64 + k) * 192 + 128 + j0];
        u64 ha0 = pack2(ha.x, ha.x), ha1 = pack2(ha.y, ha.y);
        u64 hb0 = pack2(hb.x, hb.x), hb1 = pack2(hb.y, hb.y);
        aR[0][0] = fma2(ha0, wrA.x, aR[0][0]);  aR[0][1] = fma2(ha1, wrA.x, aR[0][1]);
        aR[1][0] = fma2(ha0, wrA.y, aR[1][0]);  aR[1][1] = fma2(ha1, wrA.y, aR[1][1]);
        aZ[0][0] = fma2(ha0, wzA.x, aZ[0][0]);  aZ[0][1] = fma2(ha1, wzA.x, aZ[0][1]);
        aZ[1][0] = fma2(ha0, wzA.y, aZ[1][0]);  aZ[1][1] = fma2(ha1, wzA.y, aZ[1][1]);
        nI[0][0] = fma2(ha0, wnA.x, nI[0][0]);  nI[0][1] = fma2(ha1, wnA.x, nI[0][1]);
        nI[1][0] = fma2(ha0, wnA.y, nI[1][0]);  nI[1][1] = fma2(ha1, wnA.y, nI[1][1]);
        aR[0][0] = fma2(hb0, wrB.x, aR[0][0]);  aR[0][1] = fma2(hb1, wrB.x, aR[0][1]);
        aR[1][0] = fma2(hb0, wrB.y, aR[1][0]);  aR[1][1] = fma2(hb1, wrB.y, aR[1][1]);
        aZ[0][0] = fma2(hb0, wzB.x, aZ[0][0]);  aZ[0][1] = fma2(hb1, wzB.x, aZ[0][1]);
        aZ[1][0] = fma2(hb0, wzB.y, aZ[1][0]);  aZ[1][1] = fma2(hb1, wzB.y, aZ[1][1]);
        nH[0][0] = fma2(hb0, wnB.x, nH[0][0]);  nH[0][1] = fma2(hb1, wnB.x, nH[0][1]);
        nH[1][0] = fma2(hb0, wnB.y, nH[1][0]);  nH[1][1] = fma2(hb1, wnB.y, nH[1][1]);
    }
}

__device__ __forceinline__ void init_b(const float* __restrict__ b,
                                       u64 (&aR)[2][2], u64 (&aZ)[2][2],
                                       u64 (&nI)[2][2], u64 (&nH)[2][2], int j0) {
#pragma unroll
    for (int p = 0; p < 2; p++) {
        int base = j0 + 2 * p;
        u64 bR = *(const u64*)&b[base];
        u64 bZ = *(const u64*)&b[64 + base];
        u64 bI = *(const u64*)&b[128 + base];
        u64 bH = *(const u64*)&b[192 + base];
#pragma unroll
        for (int ri = 0; ri < 2; ri++) { aR[p][ri] = bR; aZ[p][ri] = bZ; nI[p][ri] = bI; nH[p][ri] = bH; }
    }
}

// gates + state update; optionally also emits decoder-head partials.
template <bool HEAD>
__device__ __forceinline__ void gru_update2(const float* __restrict__ hsrc, float* __restrict__ hdst,
                                            u64 (&aR)[2][2], u64 (&aZ)[2][2],
                                            u64 (&nI)[2][2], u64 (&nH)[2][2],
                                            int r0, int j0,
                                            const float* wo, float* partrow) {
    float part[2] = {0.0f, 0.0f};
#pragma unroll
    for (int p = 0; p < 2; p++) {
        int c0 = j0 + 2 * p, c1 = c0 + 1;
        float2 hA = *(const float2*)&hsrc[c0 * 64 + r0];
        float2 hB = *(const float2*)&hsrc[c1 * 64 + r0];
        float oA[2], oB[2];
        const float hAa[2] = {hA.x, hA.y};
        const float hBa[2] = {hB.x, hB.y};
#pragma unroll
        for (int ri = 0; ri < 2; ri++) {
            float arl, arh, azl, azh, nil, nih, nhl, nhh;
            unpack2(aR[p][ri], arl, arh);
            unpack2(aZ[p][ri], azl, azh);
            unpack2(nI[p][ri], nil, nih);
            unpack2(nH[p][ri], nhl, nhh);
            float rA = sigm_t(arl), rB = sigm_t(arh);
            float zA = sigm_t(azl), zB = sigm_t(azh);
            float nA = tanh_t(fmaf(rA, nhl, nil));
            float nB = tanh_t(fmaf(rB, nhh, nih));
            oA[ri] = fmaf(zA, hAa[ri] - nA, nA);
            oB[ri] = fmaf(zB, hBa[ri] - nB, nB);
            if (HEAD) part[ri] = fmaf(oA[ri], wo[2 * p], fmaf(oB[ri], wo[2 * p + 1], part[ri]));
        }
        *(float2*)&hdst[c0 * 64 + r0] = make_float2(oA[0], oA[1]);
        *(float2*)&hdst[c1 * 64 + r0] = make_float2(oB[0], oB[1]);
    }
    if (HEAD) *(float2*)&partrow[r0] = make_float2(part[0], part[1]);
}

__device__ void load_weights(float* __restrict__ sm,
                             const float* __restrict__ Wih0, int nin,
                             const float* __restrict__ Whh0,
                             const float* __restrict__ bih0, const float* __restrict__ bhh0,
                             const float* __restrict__ Wih1, const float* __restrict__ Whh1,
                             const float* __restrict__ bih1, const float* __restrict__ bhh1,
                             int tid) {
    float* wt0 = sm + OFF_WT0;
    float* wc1 = sm + OFF_WC1;
    float* b0  = sm + OFF_B0;
    float* b1  = sm + OFF_B1;
    float* w0s = sm + OFF_W0S;
    for (int i = tid; i < 12288; i += NT) { int j = i >> 6, k = i & 63; wt0[k * 192 + j] = Whh0[i]; }
    for (int i = tid; i < 12288; i += NT) { int j = i >> 6, k = i & 63; wc1[k * 192 + j] = Wih1[i]; }
    for (int i = tid; i < 12288; i += NT) { int j = i >> 6, k = i & 63; wc1[(64 + k) * 192 + j] = Whh1[i]; }
    for (int i = tid; i < 192 * nin; i += NT) { int c = i / 192, gj = i % 192; w0s[i] = Wih0[gj * nin + c]; }
    if (tid < 64) {
        b0[tid]       = bih0[tid]       + bhh0[tid];
        b0[64 + tid]  = bih0[64 + tid]  + bhh0[64 + tid];
        b0[128 + tid] = bih0[128 + tid];
        b0[192 + tid] = bhh0[128 + tid];
        b1[tid]       = bih1[tid]       + bhh1[tid];
        b1[64 + tid]  = bih1[64 + tid]  + bhh1[64 + tid];
        b1[128 + tid] = bih1[128 + tid];
        b1[192 + tid] = bhh1[128 + tid];
    }
}

extern "C" __global__ void __launch_bounds__(NT, 1)
gru_controller_kernel(const float* __restrict__ x,
                      const float* eWih0, const float* eWhh0, const float* ebih0, const float* ebhh0,
                      const float* eWih1, const float* eWhh1, const float* ebih1, const float* ebhh1,
                      const float* dWih0, const float* dWhh0, const float* dbih0, const float* dbhh0,
                      const float* dWih1, const float* dWhh1, const float* dbih1, const float* dbhh1,
                      const float* __restrict__ outW, const float* __restrict__ outb,
                      float* __restrict__ out) {
    extern __shared__ float sm[];
    float* wt0   = sm + OFF_WT0;
    float* wc1   = sm + OFF_WC1;
    float* b0    = sm + OFF_B0;
    float* b1    = sm + OFF_B1;
    float* w0s   = sm + OFF_W0S;
    float* xst   = sm + OFF_XST;
    float* prevb = sm + OFF_PREV;
    float* outw  = sm + OFF_OUTW;
    float* partb = sm + OFF_PART;

    const int tid = threadIdx.x;
    const int rt = tid & 31, ct = tid >> 5;     // 32 row-groups x 16 warps
    const int r0 = rt * 2, j0 = ct * 4;         // 2 rows, 4 cols per thread
    const int rbase = blockIdx.x * 64;

    for (int i = tid; i < 16384; i += NT) sm[OFF_H0A + i] = 0.0f;
    load_weights(sm, eWih0, 2, eWhh0, ebih0, ebhh0, eWih1, eWhh1, ebih1, ebhh1, tid);
    if (tid < 64) outw[tid] = outW[tid];
    if (tid < 128) { // stage x for t=0
        int r = tid >> 1, c = tid & 1;
        xst[c * 64 + r] = x[((long)(rbase + r) * TIN) * 2 + c];
    }
    __syncthreads();

    u64 aR[2][2], aZ[2][2], nI[2][2], nH[2][2];
    int p = 0;

    // ===================== encoder (1 barrier/step) =====================
    for (int t = 0; t < TIN; t++) {
        const float* h0s = sm + (p ? OFF_H0B : OFF_H0A);
        float*       h0d = sm + (p ? OFF_H0A : OFF_H0B);
        const float* h1s = sm + (p ? OFF_H1B : OFF_H1A);
        float*       h1d = sm + (p ? OFF_H1A : OFF_H1B);
        const float* xb  = xst + (t & 1) * 128;

        // stage x for t+1 into the OTHER slot (read slot is t&1; no conflict)
        if (t + 1 < TIN && tid < 128) {
            int r = tid >> 1, c = tid & 1;
            xst[((t + 1) & 1) * 128 + c * 64 + r] = x[((long)(rbase + r) * TIN + (t + 1)) * 2 + c];
        }

        // layer0 init: bias + x @ Wih0^T
        {
            float2 x0v = *(const float2*)&xb[r0];
            float2 x1v = *(const float2*)&xb[64 + r0];
            u64 xd00 = pack2(x0v.x, x0v.x), xd01 = pack2(x0v.y, x0v.y);
            u64 xd10 = pack2(x1v.x, x1v.x), xd11 = pack2(x1v.y, x1v.y);
#pragma unroll
            for (int pp = 0; pp < 2; pp++) {
                int base = j0 + 2 * pp;
                u64 bR = *(const u64*)&b0[base];
                u64 bZ = *(const u64*)&b0[64 + base];
                u64 bI = *(const u64*)&b0[128 + base];
                u64 bH = *(const u64*)&b0[192 + base];
                u64 wR0 = *(const u64*)&w0s[base],        wR1 = *(const u64*)&w0s[192 + base];
                u64 wZ0 = *(const u64*)&w0s[64 + base],   wZ1 = *(const u64*)&w0s[192 + 64 + base];
                u64 wN0 = *(const u64*)&w0s[128 + base],  wN1 = *(const u64*)&w0s[192 + 128 + base];
                aR[pp][0] = fma2(xd10, wR1, fma2(xd00, wR0, bR));
                aR[pp][1] = fma2(xd11, wR1, fma2(xd01, wR0, bR));
                aZ[pp][0] = fma2(xd10, wZ1, fma2(xd00, wZ0, bZ));
                aZ[pp][1] = fma2(xd11, wZ1, fma2(xd01, wZ0, bZ));
                nI[pp][0] = fma2(xd10, wN1, fma2(xd00, wN0, bI));
                nI[pp][1] = fma2(xd11, wN1, fma2(xd01, wN0, bI));
                nH[pp][0] = bH;
                nH[pp][1] = bH;
            }
        }
        kloop64p(h0s, wt0, aR, aZ, nH, r0, j0);
        gru_update2<false>(h0s, h0d, aR, aZ, nI, nH, r0, j0, 0, 0);
        __syncthreads();   // the ONE barrier: layer0-write -> layer1-read

        init_b(b1, aR, aZ, nI, nH, j0);
        kloop_l1(h0d, h1s, wc1, aR, aZ, nI, nH, r0, j0);
        gru_update2<false>(h1s, h1d, aR, aZ, nI, nH, r0, j0, 0, 0);
        // no trailing barrier: all step-t+1 pre-sync reads are of data sealed
        // before this step's barrier (see R6 hazard analysis)
        p ^= 1;
    }

    // ===================== swap to decoder weights =====================
    __syncthreads();   // encoder warps may still be reading wt0/wc1
    load_weights(sm, dWih0, 1, dWhh0, dbih0, dbhh0, dWih1, dWhh1, dbih1, dbhh1, tid);
    if (tid < 64) prevb[tid] = 0.0f;
    __syncthreads();
    const float ob = outb[0];
    float wo[4];
#pragma unroll
    for (int c = 0; c < 4; c++) wo[c] = outw[j0 + c];   // warp-uniform broadcast

    // ===================== decoder =====================
    for (int t = 0; t < TOUT; t++) {
        const float* h0s = sm + (p ? OFF_H0B : OFF_H0A);
        float*       h0d = sm + (p ? OFF_H0A : OFF_H0B);
        const float* h1s = sm + (p ? OFF_H1B : OFF_H1A);
        float*       h1d = sm + (p ? OFF_H1A : OFF_H1B);

        // layer0 init: bias + prev * Wih0 (nin=1)
        {
            float2 pv = *(const float2*)&prevb[r0];
            u64 pd0 = pack2(pv.x, pv.x), pd1 = pack2(pv.y, pv.y);
#pragma unroll
            for (int pp = 0; pp < 2; pp++) {
                int base = j0 + 2 * pp;
                u64 bR = *(const u64*)&b0[base];
                u64 bZ = *(const u64*)&b0[64 + base];
                u64 bI = *(const u64*)&b0[128 + base];
                u64 bH = *(const u64*)&b0[192 + base];
                u64 wR = *(const u64*)&w0s[base];
                u64 wZ = *(const u64*)&w0s[64 + base];
                u64 wN = *(const u64*)&w0s[128 + base];
                aR[pp][0] = fma2(pd0, wR, bR);
                aR[pp][1] = fma2(pd1, wR, bR);
                aZ[pp][0] = fma2(pd0, wZ, bZ);
                aZ[pp][1] = fma2(pd1, wZ, bZ);
                nI[pp][0] = fma2(pd0, wN, bI);
                nI[pp][1] = fma2(pd1, wN, bI);
                nH[pp][0] = bH;
                nH[pp][1] = bH;
            }
        }
        kloop64p(h0s, wt0, aR, aZ, nH, r0, j0);
        gru_update2<false>(h0s, h0d, aR, aZ, nI, nH, r0, j0, 0, 0);
        __syncthreads();

        init_b(b1, aR, aZ, nI, nH, j0);
        kloop_l1(h0d, h1s, wc1, aR, aZ, nI, nH, r0, j0);
        gru_update2<true>(h1s, h1d, aR, aZ, nI, nH, r0, j0, wo, partb + ct * 64);
        __syncthreads();

        // head reduce: out[r] = ob + sum_ct part[ct][r]
        if (tid < 64) {
            float acc = ob;
#pragma unroll
            for (int c = 0; c < 16; c++) acc += partb[c * 64 + tid];
            prevb[tid] = acc;
            out[(long)(rbase + tid) * TOUT + t] = acc;
        }
        __syncthreads();
        p ^= 1;
    }
}

extern "C" void kernel_launch(void* const* d_in, const int* in_sizes, int n_in,
                              void* d_out, int out_size) {
    const float* x     = (const float*)d_in[0];
    const float* eWih0 = (const float*)d_in[1];
    const float* eWhh0 = (const float*)d_in[2];
    const float* ebih0 = (const float*)d_in[3];
    const float* ebhh0 = (const float*)d_in[4];
    const float* eWih1 = (const float*)d_in[5];
    const float* eWhh1 = (const float*)d_in[6];
    const float* ebih1 = (const float*)d_in[7];
    const float* ebhh1 = (const float*)d_in[8];
    const float* dWih0 = (const float*)d_in[9];
    const float* dWhh0 = (const float*)d_in[10];
    const float* dbih0 = (const float*)d_in[11];
    const float* dbhh0 = (const float*)d_in[12];
    const float* dWih1 = (const float*)d_in[13];
    const float* dWhh1 = (const float*)d_in[14];
    const float* dbih1 = (const float*)d_in[15];
    const float* dbhh1 = (const float*)d_in[16];
    const float* outW  = (const float*)d_in[17];
    const float* outb  = (const float*)d_in[18];
    float* out = (float*)d_out;

    cudaFuncSetAttribute(gru_controller_kernel,
                         cudaFuncAttributeMaxDynamicSharedMemorySize, SMEM_BYTES);
    gru_controller_kernel<<<128, NT, SMEM_BYTES>>>(
        x, eWih0, eWhh0, ebih0, ebhh0, eWih1, eWhh1, ebih1, ebhh1,
        dWih0, dWhh0, dbih0, dbhh0, dWih1, dWhh1, dbih1, dbhh1,
        outW, outb, out);
}

// round 8
// speedup vs baseline: 8.6010x; 3.8465x over previous
#include <cuda_runtime.h>
#include <cstdint>

// GRUController via tensor cores: mma.sync.m16n8k8 tf32, fp32 epilogue/state update.
// 128 CTAs x 64 rows, 256 threads = 8 warps = 2 row-groups(32) x 4 col-groups(16).

typedef uint32_t u32;

#define TIN  512
#define TOUT 180
#define NT   256
#define HS   68     // h row stride in floats (bank-conflict-free A-frags)

// smem word offsets
#define OFF_BL0   0        // 192 frags * 64 = 12288 (L0 Whh B-frags, tf32)
#define OFF_BL1   12288    // 384 frags * 64 = 24576 (L1 [Wih|Whh] B-frags)
#define OFF_H0A   36864    // 64*68 = 4352
#define OFF_H0B   41216
#define OFF_H1A   45568
#define OFF_H1B   49920
#define OFF_B0    54272    // 256: bR,bZ,bI,bH
#define OFF_B1    54528    // 256
#define OFF_W0S   54784    // 384: layer0 input weights [j][2]
#define OFF_XST   55168    // 2 slots * 64 rows * 2
#define OFF_OUTW  55424    // 64
#define OFF_PART  55488    // 4 jg * 64 rows
#define SMEM_FLOATS 55744
#define SMEM_BYTES  (SMEM_FLOATS * 4)   // 222,976 B

__device__ __forceinline__ float tanh_t(float x) {
    float y; asm("tanh.approx.f32 %0,%1;" : "=f"(y) : "f"(x)); return y;
}
__device__ __forceinline__ float sigm_t(float x) {
    return fmaf(tanh_t(0.5f * x), 0.5f, 0.5f);
}
__device__ __forceinline__ float to_tf32(float f) {
    u32 r; asm("cvt.rna.tf32.f32 %0,%1;" : "=r"(r) : "f"(f)); return __uint_as_float(r);
}
__device__ __forceinline__ void mma8(float* c, u32 a0, u32 a1, u32 a2, u32 a3,
                                     u32 b0, u32 b1) {
    asm volatile(
        "mma.sync.aligned.m16n8k8.row.col.f32.tf32.tf32.f32 "
        "{%0,%1,%2,%3},{%4,%5,%6,%7},{%8,%9},{%0,%1,%2,%3};"
        : "+f"(c[0]), "+f"(c[1]), "+f"(c[2]), "+f"(c[3])
        : "r"(a0), "r"(a1), "r"(a2), "r"(a3), "r"(b0), "r"(b1));
}

__device__ void load_weights_tc(float* __restrict__ sm,
                                const float* __restrict__ Wih0, int nin,
                                const float* __restrict__ Whh0,
                                const float* __restrict__ bih0, const float* __restrict__ bhh0,
                                const float* __restrict__ Wih1, const float* __restrict__ Whh1,
                                const float* __restrict__ bih1, const float* __restrict__ bhh1,
                                int tid) {
    // L0 B-frags: frag f = ga*64 + nt*8 + c ; lane l: b0=W[row][c*8+tq], b1=+4
    for (int i = tid; i < 192 * 32; i += NT) {
        int f = i >> 5, l = i & 31;
        int ga = f >> 6, rem = f & 63, nt = rem >> 3, c = rem & 7;
        int row = ga * 64 + nt * 8 + (l >> 2);
        int k0 = c * 8 + (l & 3);
        sm[OFF_BL0 + f * 64 + l * 2]     = to_tf32(Whh0[row * 64 + k0]);
        sm[OFF_BL0 + f * 64 + l * 2 + 1] = to_tf32(Whh0[row * 64 + k0 + 4]);
    }
    // L1 B-frags: f = ga*128 + nt*16 + c ; c<8 -> Wih1, c>=8 -> Whh1
    for (int i = tid; i < 384 * 32; i += NT) {
        int f = i >> 5, l = i & 31;
        int ga = f >> 7, rem = f & 127, nt = rem >> 4, c = rem & 15;
        int row = ga * 64 + nt * 8 + (l >> 2);
        int k0 = (c & 7) * 8 + (l & 3);
        const float* src = (c < 8) ? Wih1 : Whh1;
        sm[OFF_BL1 + f * 64 + l * 2]     = to_tf32(src[row * 64 + k0]);
        sm[OFF_BL1 + f * 64 + l * 2 + 1] = to_tf32(src[row * 64 + k0 + 4]);
    }
    for (int j = tid; j < 192; j += NT) {
        sm[OFF_W0S + j * 2]     = Wih0[j * nin];
        sm[OFF_W0S + j * 2 + 1] = (nin == 2) ? Wih0[j * 2 + 1] : 0.0f;
    }
    if (tid < 64) {
        sm[OFF_B0 + tid]       = bih0[tid]       + bhh0[tid];
        sm[OFF_B0 + 64 + tid]  = bih0[64 + tid]  + bhh0[64 + tid];
        sm[OFF_B0 + 128 + tid] = bih0[128 + tid];
        sm[OFF_B0 + 192 + tid] = bhh0[128 + tid];
        sm[OFF_B1 + tid]       = bih1[tid]       + bhh1[tid];
        sm[OFF_B1 + 64 + tid]  = bih1[64 + tid]  + bhh1[64 + tid];
        sm[OFF_B1 + 128 + tid] = bih1[128 + tid];
        sm[OFF_B1 + 192 + tid] = bhh1[128 + tid];
    }
}

extern "C" __global__ void __launch_bounds__(NT, 1)
gru_controller_kernel(const float* __restrict__ x,
                      const float* eWih0, const float* eWhh0, const float* ebih0, const float* ebhh0,
                      const float* eWih1, const float* eWhh1, const float* ebih1, const float* ebhh1,
                      const float* dWih0, const float* dWhh0, const float* dbih0, const float* dbhh0,
                      const float* dWih1, const float* dWhh1, const float* dbih1, const float* dbhh1,
                      const float* __restrict__ outW, const float* __restrict__ outb,
                      float* __restrict__ out) {
    extern __shared__ float sm[];
    const int tid = threadIdx.x;
    const int w = tid >> 5, l = tid & 31;
    const int mg = w >> 2, jg = w & 3;
    const int g = l >> 2, tq = l & 3;
    const int rb0 = mg * 32;
    const int rbase = blockIdx.x * 64;

    float aR[2][2][4], aZ[2][2][4], aI[2][2][4], aH[2][2][4];

    // ---------------- helpers ----------------
    // init accumulators: bias (+ optional x @ Wih0^T from xst slot)
    auto init_gates = [&](const float* b, bool withX, int slot) {
        float2 xv[2][2];
        if (withX) {
#pragma unroll
            for (int mt = 0; mt < 2; mt++) {
                xv[mt][0] = *(const float2*)&sm[OFF_XST + slot * 128 + (rb0 + mt * 16 + g) * 2];
                xv[mt][1] = *(const float2*)&sm[OFF_XST + slot * 128 + (rb0 + mt * 16 + g + 8) * 2];
            }
        }
#pragma unroll
        for (int ntl = 0; ntl < 2; ntl++) {
            int col0 = (jg * 2 + ntl) * 8 + 2 * tq;
            float2 bR = *(const float2*)&b[col0];
            float2 bZ = *(const float2*)&b[64 + col0];
            float2 bI = *(const float2*)&b[128 + col0];
            float2 bH = *(const float2*)&b[192 + col0];
            if (withX) {
                float2 wr0 = *(const float2*)&sm[OFF_W0S + col0 * 2];
                float2 wr1 = *(const float2*)&sm[OFF_W0S + (col0 + 1) * 2];
                float2 wz0 = *(const float2*)&sm[OFF_W0S + (64 + col0) * 2];
                float2 wz1 = *(const float2*)&sm[OFF_W0S + (64 + col0 + 1) * 2];
                float2 wn0 = *(const float2*)&sm[OFF_W0S + (128 + col0) * 2];
                float2 wn1 = *(const float2*)&sm[OFF_W0S + (128 + col0 + 1) * 2];
#pragma unroll
                for (int mt = 0; mt < 2; mt++) {
#pragma unroll
                    for (int h = 0; h < 2; h++) {   // h=0: rows g, h=1: rows g+8 (q = 2h, 2h+1)
                        float x0 = xv[mt][h].x, x1 = xv[mt][h].y;
                        aR[mt][ntl][2 * h]     = bR.x + x0 * wr0.x + x1 * wr0.y;
                        aR[mt][ntl][2 * h + 1] = bR.y + x0 * wr1.x + x1 * wr1.y;
                        aZ[mt][ntl][2 * h]     = bZ.x + x0 * wz0.x + x1 * wz0.y;
                        aZ[mt][ntl][2 * h + 1] = bZ.y + x0 * wz1.x + x1 * wz1.y;
                        aI[mt][ntl][2 * h]     = bI.x + x0 * wn0.x + x1 * wn0.y;
                        aI[mt][ntl][2 * h + 1] = bI.y + x0 * wn1.x + x1 * wn1.y;
                        aH[mt][ntl][2 * h]     = bH.x;
                        aH[mt][ntl][2 * h + 1] = bH.y;
                    }
                }
            } else {
#pragma unroll
                for (int mt = 0; mt < 2; mt++) {
                    aR[mt][ntl][0] = bR.x; aR[mt][ntl][1] = bR.y; aR[mt][ntl][2] = bR.x; aR[mt][ntl][3] = bR.y;
                    aZ[mt][ntl][0] = bZ.x; aZ[mt][ntl][1] = bZ.y; aZ[mt][ntl][2] = bZ.x; aZ[mt][ntl][3] = bZ.y;
                    aI[mt][ntl][0] = bI.x; aI[mt][ntl][1] = bI.y; aI[mt][ntl][2] = bI.x; aI[mt][ntl][3] = bI.y;
                    aH[mt][ntl][0] = bH.x; aH[mt][ntl][1] = bH.y; aH[mt][ntl][2] = bH.x; aH[mt][ntl][3] = bH.y;
                }
            }
        }
    };

    // L0 contraction: h @ Whh0^T -> aR,aZ,aH
    auto mma_l0 = [&](const float* hs) {
        const float* rp[4] = { hs + (rb0 + g) * HS,      hs + (rb0 + g + 8) * HS,
                               hs + (rb0 + 16 + g) * HS, hs + (rb0 + 24 + g) * HS };
#pragma unroll
        for (int c = 0; c < 8; c++) {
            int k0 = c * 8 + tq;
            u32 a[2][4];
#pragma unroll
            for (int mt = 0; mt < 2; mt++) {
                a[mt][0] = __float_as_uint(rp[mt * 2][k0]);
                a[mt][1] = __float_as_uint(rp[mt * 2 + 1][k0]);
                a[mt][2] = __float_as_uint(rp[mt * 2][k0 + 4]);
                a[mt][3] = __float_as_uint(rp[mt * 2 + 1][k0 + 4]);
            }
#pragma unroll
            for (int ntl = 0; ntl < 2; ntl++) {
                int nt = jg * 2 + ntl;
                uint2 bR = *(const uint2*)&sm[OFF_BL0 + (0 * 64 + nt * 8 + c) * 64 + l * 2];
                uint2 bZ = *(const uint2*)&sm[OFF_BL0 + (1 * 64 + nt * 8 + c) * 64 + l * 2];
                uint2 bN = *(const uint2*)&sm[OFF_BL0 + (2 * 64 + nt * 8 + c) * 64 + l * 2];
#pragma unroll
                for (int mt = 0; mt < 2; mt++) {
                    mma8(aR[mt][ntl], a[mt][0], a[mt][1], a[mt][2], a[mt][3], bR.x, bR.y);
                    mma8(aZ[mt][ntl], a[mt][0], a[mt][1], a[mt][2], a[mt][3], bZ.x, bZ.y);
                    mma8(aH[mt][ntl], a[mt][0], a[mt][1], a[mt][2], a[mt][3], bN.x, bN.y);
                }
            }
        }
    };

    // L1 contraction: h0 @ Wih1^T (c<8 -> aI) + h1 @ Whh1^T (c>=8 -> aH); r,z both
    auto mma_l1 = [&](const float* h0, const float* h1) {
#pragma unroll
        for (int c = 0; c < 16; c++) {
            const float* hs = (c < 8) ? h0 : h1;
            int k0 = (c & 7) * 8 + tq;
            u32 a[2][4];
#pragma unroll
            for (int mt = 0; mt < 2; mt++) {
                const float* plo = hs + (rb0 + mt * 16 + g) * HS;
                const float* phi = hs + (rb0 + mt * 16 + g + 8) * HS;
                a[mt][0] = __float_as_uint(plo[k0]);
                a[mt][1] = __float_as_uint(phi[k0]);
                a[mt][2] = __float_as_uint(plo[k0 + 4]);
                a[mt][3] = __float_as_uint(phi[k0 + 4]);
            }
#pragma unroll
            for (int ntl = 0; ntl < 2; ntl++) {
                int nt = jg * 2 + ntl;
                uint2 bR = *(const uint2*)&sm[OFF_BL1 + (0 * 128 + nt * 16 + c) * 64 + l * 2];
                uint2 bZ = *(const uint2*)&sm[OFF_BL1 + (1 * 128 + nt * 16 + c) * 64 + l * 2];
                uint2 bN = *(const uint2*)&sm[OFF_BL1 + (2 * 128 + nt * 16 + c) * 64 + l * 2];
#pragma unroll
                for (int mt = 0; mt < 2; mt++) {
                    mma8(aR[mt][ntl], a[mt][0], a[mt][1], a[mt][2], a[mt][3], bR.x, bR.y);
                    mma8(aZ[mt][ntl], a[mt][0], a[mt][1], a[mt][2], a[mt][3], bZ.x, bZ.y);
                    if (c < 8) mma8(aI[mt][ntl], a[mt][0], a[mt][1], a[mt][2], a[mt][3], bN.x, bN.y);
                    else       mma8(aH[mt][ntl], a[mt][0], a[mt][1], a[mt][2], a[mt][3], bN.x, bN.y);
                }
            }
        }
    };

    // gates + state update (+ optional output-head partials)
    auto update = [&](const float* hs, float* hd, bool head) {
        float pr[2][2] = {{0.0f, 0.0f}, {0.0f, 0.0f}};
#pragma unroll
        for (int mt = 0; mt < 2; mt++)
#pragma unroll
            for (int ntl = 0; ntl < 2; ntl++) {
                int col = (jg * 2 + ntl) * 8 + 2 * tq;
                int rlo = rb0 + mt * 16 + g, rhi = rlo + 8;
                float2 hlo = *(const float2*)&hs[rlo * HS + col];
                float2 hhi = *(const float2*)&hs[rhi * HS + col];
                float2 wo = head ? *(const float2*)&sm[OFF_OUTW + col] : make_float2(0.f, 0.f);
                float o[4];
                const float hold[4] = {hlo.x, hlo.y, hhi.x, hhi.y};
#pragma unroll
                for (int q = 0; q < 4; q++) {
                    float r = sigm_t(aR[mt][ntl][q]);
                    float z = sigm_t(aZ[mt][ntl][q]);
                    float n = tanh_t(fmaf(r, aH[mt][ntl][q], aI[mt][ntl][q]));
                    o[q] = to_tf32(fmaf(z, hold[q] - n, n));
                }
                *(float2*)&hd[rlo * HS + col] = make_float2(o[0], o[1]);
                *(float2*)&hd[rhi * HS + col] = make_float2(o[2], o[3]);
                if (head) {
                    pr[mt][0] = fmaf(o[0], wo.x, fmaf(o[1], wo.y, pr[mt][0]));
                    pr[mt][1] = fmaf(o[2], wo.x, fmaf(o[3], wo.y, pr[mt][1]));
                }
            }
        if (head) {
#pragma unroll
            for (int mt = 0; mt < 2; mt++)
#pragma unroll
                for (int h = 0; h < 2; h++) {
                    float v = pr[mt][h];
                    v += __shfl_xor_sync(0xffffffffu, v, 1);
                    v += __shfl_xor_sync(0xffffffffu, v, 2);
                    if (tq == 0)
                        sm[OFF_PART + jg * 64 + rb0 + mt * 16 + h * 8 + g] = v;
                }
        }
    };

    // ---------------- setup ----------------
    for (int i = tid; i < 4 * 64 * HS; i += NT) sm[OFF_H0A + i] = 0.0f;
    load_weights_tc(sm, eWih0, 2, eWhh0, ebih0, ebhh0, eWih1, eWhh1, ebih1, ebhh1, tid);
    if (tid < 64) sm[OFF_OUTW + tid] = outW[tid];
    if (tid < 128) {  // stage x for t=0 into slot 0
        int r = tid >> 1, c = tid & 1;
        sm[OFF_XST + r * 2 + c] = x[((long)(rbase + r) * TIN) * 2 + c];
    }
    __syncthreads();

    int p = 0;
    // ================= encoder (1 barrier/step) =================
    for (int t = 0; t < TIN; t++) {
        const float* h0s = sm + (p ? OFF_H0B : OFF_H0A);
        float*       h0d = sm + (p ? OFF_H0A : OFF_H0B);
        const float* h1s = sm + (p ? OFF_H1B : OFF_H1A);
        float*       h1d = sm + (p ? OFF_H1A : OFF_H1B);

        if (t + 1 < TIN && tid < 128) {  // stage next x into other slot
            int r = tid >> 1, c = tid & 1;
            sm[OFF_XST + ((t + 1) & 1) * 128 + r * 2 + c] =
                x[((long)(rbase + r) * TIN + (t + 1)) * 2 + c];
        }

        init_gates(sm + OFF_B0, true, t & 1);
        mma_l0(h0s);
        update(h0s, h0d, false);
        __syncthreads();   // layer0-write -> layer1-read

        init_gates(sm + OFF_B1, false, 0);
        mma_l1(h0d, h1s);
        update(h1s, h1d, false);
        p ^= 1;
    }

    // ================= swap to decoder weights =================
    __syncthreads();
    load_weights_tc(sm, dWih0, 1, dWhh0, dbih0, dbhh0, dWih1, dWhh1, dbih1, dbhh1, tid);
    if (tid < 64) {  // prev = 0 in slot 0 (channel 1 stays 0; w0s ch1 weights are 0)
        sm[OFF_XST + tid * 2]     = 0.0f;
        sm[OFF_XST + tid * 2 + 1] = 0.0f;
    }
    __syncthreads();
    const float ob = outb[0];

    // ================= decoder =================
    for (int t = 0; t < TOUT; t++) {
        const float* h0s = sm + (p ? OFF_H0B : OFF_H0A);
        float*       h0d = sm + (p ? OFF_H0A : OFF_H0B);
        const float* h1s = sm + (p ? OFF_H1B : OFF_H1A);
        float*       h1d = sm + (p ? OFF_H1A : OFF_H1B);

        init_gates(sm + OFF_B0, true, 0);   // prev in slot 0
        mma_l0(h0s);
        update(h0s, h0d, false);
        __syncthreads();

        init_gates(sm + OFF_B1, false, 0);
        mma_l1(h0d, h1s);
        update(h1s, h1d, true);
        __syncthreads();

        if (tid < 64) {
            float acc = ob + sm[OFF_PART + tid] + sm[OFF_PART + 64 + tid]
                           + sm[OFF_PART + 128 + tid] + sm[OFF_PART + 192 + tid];
            sm[OFF_XST + tid * 2] = acc;     // prev for next step
            out[(long)(rbase + tid) * TOUT + t] = acc;
        }
        __syncthreads();
        p ^= 1;
    }
}

extern "C" void kernel_launch(void* const* d_in, const int* in_sizes, int n_in,
                              void* d_out, int out_size) {
    const float* x     = (const float*)d_in[0];
    const float* eWih0 = (const float*)d_in[1];
    const float* eWhh0 = (const float*)d_in[2];
    const float* ebih0 = (const float*)d_in[3];
    const float* ebhh0 = (const float*)d_in[4];
    const float* eWih1 = (const float*)d_in[5];
    const float* eWhh1 = (const float*)d_in[6];
    const float* ebih1 = (const float*)d_in[7];
    const float* ebhh1 = (const float*)d_in[8];
    const float* dWih0 = (const float*)d_in[9];
    const float* dWhh0 = (const float*)d_in[10];
    const float* dbih0 = (const float*)d_in[11];
    const float* dbhh0 = (const float*)d_in[12];
    const float* dWih1 = (const float*)d_in[13];
    const float* dWhh1 = (const float*)d_in[14];
    const float* dbih1 = (const float*)d_in[15];
    const float* dbhh1 = (const float*)d_in[16];
    const float* outW  = (const float*)d_in[17];
    const float* outb  = (const float*)d_in[18];
    float* out = (float*)d_out;

    cudaFuncSetAttribute(gru_controller_kernel,
                         cudaFuncAttributeMaxDynamicSharedMemorySize, SMEM_BYTES);
    gru_controller_kernel<<<128, NT, SMEM_BYTES>>>(
        x, eWih0, eWhh0, ebih0, ebhh0, eWih1, eWhh1, ebih1, ebhh1,
        dWih0, dWhh0, dbih0, dbhh0, dWih1, dWhh1, dbih1, dbhh1,
        outW, outb, out);
}